// round 10
// baseline (speedup 1.0000x reference)
#include <cuda_runtime.h>
#include <cuda_fp16.h>
#include <cooperative_groups.h>
#include <cstdint>

namespace cg = cooperative_groups;

#define BB 32
#define T_ENC 800
#define T_DEC 400
#define EDIM 256
#define GDIM 256
#define ADIM 128
#define IDIM 80
#define CL 4              // cluster size (CTAs per batch element)
#define GSL (GDIM / CL)   // 64 hidden units per rank
#define TSL (T_ENC / CL)  // 200 encoder steps per rank
#define OSL (IDIM / CL)   // 20 output rows per rank
#define NROWS (3 * GSL)   // 192 GRU rows per rank

// Scratch (allocation-free: __device__ globals)
__device__ __align__(16) float g_enc_proj[BB * T_ENC * ADIM];   // 13.1 MB
__device__ __align__(16) float g_gx[BB * T_DEC * 3 * GDIM];     // 39.3 MB
__device__ __align__(16) __half g_wih_h[3 * GDIM * EDIM];       // fp16 ctx-part of W_ih
__device__ __align__(16) __half g_whh_h[3 * GDIM * GDIM];       // fp16 W_hh

#define SMEM_DYN (2 * NROWS * 256 * (int)sizeof(__half))        // 192 KB

__device__ __forceinline__ float fast_tanh(float x) {
    float y;
    asm("tanh.approx.f32 %0, %1;" : "=f"(y) : "f"(x));
    return y;
}
__device__ __forceinline__ float fast_sig(float x) {
    return 0.5f * fast_tanh(0.5f * x) + 0.5f;
}

// fp16 row-dot: 8 contiguous columns per lane ([lane*8, +8))
__device__ __forceinline__ float dot_row_h(const __half* wrow, int lane,
                                           __half2 x0, __half2 x1,
                                           __half2 x2, __half2 x3)
{
    const uint4 wv = *(const uint4*)(wrow + lane * 8);
    const __half2 w0 = *(const __half2*)&wv.x, w1 = *(const __half2*)&wv.y;
    const __half2 w2 = *(const __half2*)&wv.z, w3 = *(const __half2*)&wv.w;
    __half2 pa = __hfma2(w1, x1, __hmul2(w0, x0));
    __half2 pb = __hfma2(w3, x3, __hmul2(w2, x2));
    const float2 fa = __half22float2(pa), fb = __half22float2(pb);
    return (fa.x + fa.y) + (fb.x + fb.y);
}

// ---------------------------------------------------------------------------
__global__ void convert_weights(const float* __restrict__ W_ih,
                                const float* __restrict__ W_hh)
{
    const int i = blockIdx.x * blockDim.x + threadIdx.x;
    if (i < 3 * GDIM * EDIM) {
        const int r = i >> 8, c = i & 255;
        g_wih_h[i] = __float2half(W_ih[(size_t)r * 336 + 80 + c]);
        g_whh_h[i] = __float2half(W_hh[i]);
    }
}

// ---------------------------------------------------------------------------
// Generic tiled GEMM: C[M,N] = A[M,K] @ B[N,K]^T
// ---------------------------------------------------------------------------
__global__ void gemm_abt(const float* __restrict__ Ap, const float* __restrict__ Bp,
                         float* __restrict__ Cp,
                         int M, int N, int K, int lda, int ldb, int ldc)
{
    __shared__ float As[64][33];
    __shared__ float Bs[128][33];
    const int tb_m = blockIdx.y * 64;
    const int tb_n = blockIdx.x * 128;
    const int tid  = threadIdx.x;
    const int col  = tid & 127;
    const int rg   = tid >> 7;

    float acc[32];
#pragma unroll
    for (int r = 0; r < 32; r++) acc[r] = 0.f;

    for (int k0 = 0; k0 < K; k0 += 32) {
        const int kw = (K - k0 < 32) ? (K - k0) : 32;
        for (int i = tid; i < 64 * 32; i += 256) {
            int r = i >> 5, c = i & 31;
            As[r][c] = (c < kw) ? Ap[(size_t)(tb_m + r) * lda + k0 + c] : 0.f;
        }
        for (int i = tid; i < 128 * 32; i += 256) {
            int r = i >> 5, c = i & 31;
            Bs[r][c] = (c < kw) ? Bp[(size_t)(tb_n + r) * ldb + k0 + c] : 0.f;
        }
        __syncthreads();
#pragma unroll
        for (int kk = 0; kk < 32; kk++) {
            float bv = Bs[col][kk];
#pragma unroll
            for (int r = 0; r < 32; r++)
                acc[r] += As[rg * 32 + r][kk] * bv;
        }
        __syncthreads();
    }
#pragma unroll
    for (int r = 0; r < 32; r++)
        Cp[(size_t)(tb_m + rg * 32 + r) * ldc + tb_n + col] = acc[r];
}

// ---------------------------------------------------------------------------
// Clustered persistent decode. 2 cluster syncs/step.
//   warps 0-23: GRU-A(t), warps 24-31: E(t-1) (deferred output).
//   dec_proj via per-rank partials exchanged with h at sync #1.
//   softmax max-shift elided (scores bounded by sum|v_attn| ~ 5).
// ---------------------------------------------------------------------------
__global__ void __launch_bounds__(1024, 1) __cluster_dims__(CL, 1, 1)
decode_kernel(
    const float* __restrict__ enc_feat,
    const float* __restrict__ b_ih, const float* __restrict__ b_hh,
    const float* __restrict__ W_dec, const float* __restrict__ b_attn,
    const float* __restrict__ v_attn,
    const float* __restrict__ W_out, const float* __restrict__ b_out,
    float* __restrict__ pred_out, float* __restrict__ attn_out)
{
    cg::cluster_group clu = cg::this_cluster();
    const int rank = (int)clu.block_rank();
    const int b    = blockIdx.x / CL;
    const int tid  = threadIdx.x;
    const int lane = tid & 31;
    const int w    = tid >> 5;

    extern __shared__ __align__(16) __half s_wdyn[];
    __half* s_wih = s_wdyn;                 // [NROWS][256]
    __half* s_whh = s_wdyn + NROWS * 256;   // [NROWS][256]

    __shared__ __align__(16) float s_hbuf[2][GDIM];
    __shared__ __align__(16) float s_ctx[EDIM];
    __shared__ __align__(16) __half2 s_hh2[GDIM / 2];
    __shared__ __align__(16) __half2 s_ch2[EDIM / 2];
    __shared__ __align__(16) float s_grz[2 * GSL];
    __shared__ __align__(16) float s_gni[GSL];
    __shared__ __align__(16) float s_gnh[GSL];
    __shared__ __align__(16) float s_gx[NROWS];
    __shared__ __align__(16) float s_brz[2 * GSL];
    __shared__ __align__(16) float s_bni[GSL], s_bnh[GSL];
    __shared__ __align__(16) float s_battn[ADIM];
    __shared__ __align__(16) float s_bout[OSL];
    __shared__ __align__(16) float s_dp[ADIM];
    __shared__ __align__(16) float s_dpp[CL][ADIM];    // peer dp partials
    __shared__ __align__(16) float s_e[TSL];
    __shared__ __align__(16) float s_ctxp[16][EDIM];
    __shared__ __align__(16) float s_ctxpart[CL][EDIM];
    __shared__ __align__(16) float s_logits[OSL];
    __shared__ float s_red[32];
    __shared__ float s_ms[CL];                          // per-rank exp-sums
    __shared__ float s_oms[CL][2];

    // ---- one-time: fp16 weight slice to SMEM ------------------------------
#pragma unroll
    for (int g = 0; g < 3; g++) {
        const uint4* src_i = (const uint4*)(g_wih_h + (size_t)(g * GDIM + GSL * rank) * 256);
        const uint4* src_h = (const uint4*)(g_whh_h + (size_t)(g * GDIM + GSL * rank) * 256);
        uint4* dst_i = (uint4*)(s_wih + (size_t)g * GSL * 256);
        uint4* dst_h = (uint4*)(s_whh + (size_t)g * GSL * 256);
        for (int i = tid; i < GSL * 256 / 8; i += 1024) {
            dst_i[i] = src_i[i];
            dst_h[i] = src_h[i];
        }
    }
    if (tid < GSL) {
        const int u = tid;
#pragma unroll
        for (int g = 0; g < 2; g++) {
            const int row = g * GDIM + GSL * rank + u;
            s_brz[g * GSL + u] = b_ih[row] + b_hh[row];
        }
        const int rown = 2 * GDIM + GSL * rank + u;
        s_bni[u] = b_ih[rown];
        s_bnh[u] = b_hh[rown];
    }
    if (tid < ADIM) s_battn[tid] = b_attn[tid];
    if (tid < OSL)  s_bout[tid]  = b_out[OSL * rank + tid];
    if (tid < GDIM) s_hbuf[0][tid] = 0.f;
    if (tid < EDIM) s_ctx[tid] = 0.f;
    if (tid < 128) { s_hh2[tid] = __half2half2(__float2half(0.f));
                     s_ch2[tid] = __half2half2(__float2half(0.f)); }
    {
        const float* gx0 = g_gx + (size_t)(b * T_DEC) * 768;
        if (tid < NROWS) {
            const int g = tid / GSL, u = tid % GSL;
            s_gx[tid] = gx0[g * GDIM + GSL * rank + u];
        }
    }
    clu.sync();

    const float4* ep4  = (const float4*)g_enc_proj + (size_t)b * T_ENC * (ADIM / 4);
    const float4* ef4  = (const float4*)enc_feat   + (size_t)b * T_ENC * (EDIM / 4);
    const float4  vreg = ((const float4*)v_attn)[lane];
    const int tbase = TSL * rank;

    for (int t = 0; t < T_DEC; t++) {
        const int cb = t & 1, nb = cb ^ 1;

        // ===== Joint block: GRU-A(t) on warps 0-23, E(t-1) on warps 24-31 ==
        if (w < 24) {
            const __half2 xi0 = s_ch2[lane * 4 + 0], xi1 = s_ch2[lane * 4 + 1];
            const __half2 xi2 = s_ch2[lane * 4 + 2], xi3 = s_ch2[lane * 4 + 3];
            const __half2 xh0 = s_hh2[lane * 4 + 0], xh1 = s_hh2[lane * 4 + 1];
            const __half2 xh2 = s_hh2[lane * 4 + 2], xh3 = s_hh2[lane * 4 + 3];
            const int nu = (w < 16) ? 3 : 2;
#pragma unroll
            for (int j = 0; j < 3; j++) {
                if (j < nu) {
                    const int u = w + 24 * j;   // covers u = 0..63 exactly once
                    float rv = dot_row_h(s_wih + (size_t)u * 256, lane, xi0, xi1, xi2, xi3)
                             + dot_row_h(s_whh + (size_t)u * 256, lane, xh0, xh1, xh2, xh3);
                    float zv = dot_row_h(s_wih + (size_t)(64 + u) * 256, lane, xi0, xi1, xi2, xi3)
                             + dot_row_h(s_whh + (size_t)(64 + u) * 256, lane, xh0, xh1, xh2, xh3);
                    float ni = dot_row_h(s_wih + (size_t)(128 + u) * 256, lane, xi0, xi1, xi2, xi3);
                    float nh = dot_row_h(s_whh + (size_t)(128 + u) * 256, lane, xh0, xh1, xh2, xh3);
#pragma unroll
                    for (int o = 16; o > 0; o >>= 1) {
                        rv += __shfl_xor_sync(0xffffffffu, rv, o);
                        zv += __shfl_xor_sync(0xffffffffu, zv, o);
                        ni += __shfl_xor_sync(0xffffffffu, ni, o);
                        nh += __shfl_xor_sync(0xffffffffu, nh, o);
                    }
                    if (lane == 0) {
                        s_grz[u]        = rv + s_gx[u] + s_brz[u];
                        s_grz[GSL + u]  = zv + s_gx[GSL + u] + s_brz[GSL + u];
                        s_gni[u]        = ni + s_gx[2 * GSL + u] + s_bni[u];
                        s_gnh[u]        = nh + s_bnh[u];
                    }
                }
            }
        } else if (t > 0) {
            // E(t-1): h_{t-1} = s_hbuf[cb], ctx_{t-1} = s_ctx
            const int ew = w - 24;
            const int r0 = (ew < 4) ? ew * 3 : 12 + (ew - 4) * 2;
            const int nr = (ew < 4) ? 3 : 2;
            const float4 h1  = ((const float4*)s_hbuf[cb])[lane];
            const float4 h2  = ((const float4*)s_hbuf[cb])[lane + 32];
            const float4 cx1 = ((const float4*)s_ctx)[lane];
            const float4 cx2 = ((const float4*)s_ctx)[lane + 32];
            for (int rr = 0; rr < nr; rr++) {
                const int lrow = r0 + rr;
                const int row  = OSL * rank + lrow;
                const float4* wo = (const float4*)(W_out + (size_t)row * 512);
                const float4 a0 = wo[lane], a1 = wo[lane + 32];
                const float4 a2 = wo[lane + 64], a3 = wo[lane + 96];
                float acc = a0.x * h1.x + a0.y * h1.y + a0.z * h1.z + a0.w * h1.w
                          + a1.x * h2.x + a1.y * h2.y + a1.z * h2.z + a1.w * h2.w
                          + a2.x * cx1.x + a2.y * cx1.y + a2.z * cx1.z + a2.w * cx1.w
                          + a3.x * cx2.x + a3.y * cx2.y + a3.z * cx2.z + a3.w * cx2.w;
#pragma unroll
                for (int o = 16; o > 0; o >>= 1) acc += __shfl_xor_sync(0xffffffffu, acc, o);
                if (lane == 0) s_logits[lrow] = acc + s_bout[lrow];
            }
        }
        __syncthreads();

        // ---- gates: local h slice (plain store) + DSMEM to peers ----------
        if (tid < GSL) {
            const int u = tid;
            const float r = fast_sig(s_grz[u]);
            const float z = fast_sig(s_grz[GSL + u]);
            const float n = fast_tanh(s_gni[u] + r * s_gnh[u]);
            const float hn = (1.f - z) * n + z * s_hbuf[cb][GSL * rank + u];
            s_hbuf[nb][GSL * rank + u] = hn;
#pragma unroll
            for (int p = 0; p < CL; p++)
                if (p != rank)
                    *clu.map_shared_rank(&s_hbuf[nb][GSL * rank + u], p) = hn;
        }
        if (t > 0 && w == 24) {
            float lv = (lane < OSL) ? s_logits[lane] : -1e30f;
            float lm = lv;
#pragma unroll
            for (int o = 16; o > 0; o >>= 1) lm = fmaxf(lm, __shfl_xor_sync(0xffffffffu, lm, o));
            float le = (lane < OSL) ? __expf(lv - lm) : 0.f;
#pragma unroll
            for (int o = 16; o > 0; o >>= 1) le += __shfl_xor_sync(0xffffffffu, le, o);
            if (lane == 0) {
#pragma unroll
                for (int p = 0; p < CL; p++) {
                    float* d = clu.map_shared_rank(&s_oms[rank][0], p);
                    d[0] = lm; d[1] = le;
                }
            }
        }
        __syncthreads();   // local h slice visible for B'

        // ---- B': dp partials from LOCAL h slice (no wait on peers) --------
        {
            const float2 hx = *(const float2*)(&s_hbuf[nb][GSL * rank + lane * 2]);
#pragma unroll
            for (int rr = 0; rr < 4; rr++) {
                const int row = w * 4 + rr;
                const float2 wv = *(const float2*)(W_dec + (size_t)row * 256
                                                   + GSL * rank + lane * 2);
                float a = wv.x * hx.x + wv.y * hx.y;
#pragma unroll
                for (int o = 16; o > 0; o >>= 1) a += __shfl_xor_sync(0xffffffffu, a, o);
                if (lane == 0) {
#pragma unroll
                    for (int p = 0; p < CL; p++)
                        *clu.map_shared_rank(&s_dpp[rank][row], p) = a;
                }
            }
        }
        clu.sync();   // CS#1: full h + all dp partials + oms(t-1) visible

        // ---- warp 31: write output for t-1 --------------------------------
        if (t > 0 && w == 31) {
            float M2 = -1e30f;
#pragma unroll
            for (int p = 0; p < CL; p++) M2 = fmaxf(M2, s_oms[p][0]);
            float S2 = 0.f;
#pragma unroll
            for (int p = 0; p < CL; p++) S2 += s_oms[p][1] * __expf(s_oms[p][0] - M2);
            const float off = M2 + __logf(S2);
            if (lane < OSL)
                pred_out[(size_t)(b * T_DEC + (t - 1)) * IDIM + OSL * rank + lane] =
                    s_logits[lane] - off;
        }
        // ---- sum dp partials (threads 0-127) ------------------------------
        if (tid < ADIM)
            s_dp[tid] = s_dpp[0][tid] + s_dpp[1][tid] + s_dpp[2][tid]
                      + s_dpp[3][tid] + s_battn[tid];
        __syncthreads();   // s_dp ready

        // ---- C: scores with fused exp; per-warp partial sums --------------
        {
            const float4 dpv = ((const float4*)s_dp)[lane];
            float psum = 0.f;
            for (int tt = w; tt < TSL; tt += 32) {
                const float4 e = ep4[(size_t)(tbase + tt) * 32 + lane];
                float acc = fast_tanh(e.x + dpv.x) * vreg.x
                          + fast_tanh(e.y + dpv.y) * vreg.y
                          + fast_tanh(e.z + dpv.z) * vreg.z
                          + fast_tanh(e.w + dpv.w) * vreg.w;
#pragma unroll
                for (int o = 16; o > 0; o >>= 1) acc += __shfl_xor_sync(0xffffffffu, acc, o);
                if (lane == 0) {
                    const float ev = __expf(acc);   // scores bounded ~|sum v| <= ~6
                    s_e[tt] = ev;
                    psum += ev;
                }
            }
            if (lane == 0) s_red[w] = psum;
        }
        __syncthreads();   // s_e + s_red ready

        // warp 0 folds the 32 partial sums in-register, then joins D
        float S_loc = 0.f;
        if (w == 0) {
            S_loc = s_red[lane];
#pragma unroll
            for (int o = 16; o > 0; o >>= 1) S_loc += __shfl_xor_sync(0xffffffffu, S_loc, o);
        }

        // ---- D: local ctx partial (unnormalized exp weights) --------------
        {
            const int q  = tid >> 6;
            const int c4 = tid & 63;
            float4 acc = make_float4(0.f, 0.f, 0.f, 0.f);
            for (int tt = q; tt < TSL; tt += 16) {
                const float wgt = s_e[tt];
                const float4 ev = ef4[(size_t)(tbase + tt) * 64 + c4];
                acc.x += wgt * ev.x; acc.y += wgt * ev.y;
                acc.z += wgt * ev.z; acc.w += wgt * ev.w;
            }
            ((float4*)s_ctxp[q])[c4] = acc;
        }
        __syncthreads();
        if (tid < 64) {
            float4 r4 = make_float4(0.f, 0.f, 0.f, 0.f);
#pragma unroll
            for (int qq = 0; qq < 16; qq++) {
                const float4 p4 = ((const float4*)s_ctxp[qq])[tid];
                r4.x += p4.x; r4.y += p4.y; r4.z += p4.z; r4.w += p4.w;
            }
#pragma unroll
            for (int p = 0; p < CL; p++)
                ((float4*)clu.map_shared_rank(&s_ctxpart[rank][0], p))[tid] = r4;
        }
        if (tid == 0) {
#pragma unroll
            for (int p = 0; p < CL; p++)
                *clu.map_shared_rank(&s_ms[rank], p) = S_loc;
        }
        clu.sync();   // CS#2: ctx partials + exp-sums visible

        // ---- merge: global sum + ctx + attn record ------------------------
        const float S = s_ms[0] + s_ms[1] + s_ms[2] + s_ms[3];
        const float invS = 1.f / S;
        if (tid < 64) {
            float4 r4 = make_float4(0.f, 0.f, 0.f, 0.f);
#pragma unroll
            for (int p = 0; p < CL; p++) {
                const float4 p4 = ((const float4*)&s_ctxpart[p][0])[tid];
                r4.x += p4.x; r4.y += p4.y; r4.z += p4.z; r4.w += p4.w;
            }
            r4.x *= invS; r4.y *= invS; r4.z *= invS; r4.w *= invS;
            ((float4*)s_ctx)[tid] = r4;
        }
        if (tid >= 64 && tid < 64 + TSL / 4) {
            const int i = tid - 64;
            float4 e4 = ((const float4*)s_e)[i];
            e4.x *= invS; e4.y *= invS; e4.z *= invS; e4.w *= invS;
            ((float4*)(attn_out + (size_t)(b * T_DEC + t) * T_ENC + tbase))[i] = e4;
        }
        __syncthreads();

        // ---- convert h_t/ctx_t to fp16 + prefetch gx(t+1) -----------------
        if (tid < 128) {
            s_hh2[tid] = __floats2half2_rn(s_hbuf[nb][2 * tid], s_hbuf[nb][2 * tid + 1]);
            s_ch2[tid] = __floats2half2_rn(s_ctx[2 * tid], s_ctx[2 * tid + 1]);
        }
        if (t + 1 < T_DEC && tid >= 128 && tid < 128 + NROWS) {
            const int i = tid - 128;
            const float* gxn = g_gx + (size_t)(b * T_DEC + t + 1) * 768;
            const int g = i / GSL, u = i % GSL;
            s_gx[i] = gxn[g * GDIM + GSL * rank + u];
        }
        __syncthreads();
    }

    // ===== Flush: output phase for final step T_DEC-1 ======================
    {
        const int cbf = T_DEC & 1;   // buffer holding h_{T_DEC-1}
        if (w >= 24) {
            const int ew = w - 24;
            const int r0 = (ew < 4) ? ew * 3 : 12 + (ew - 4) * 2;
            const int nr = (ew < 4) ? 3 : 2;
            const float4 h1  = ((const float4*)s_hbuf[cbf])[lane];
            const float4 h2  = ((const float4*)s_hbuf[cbf])[lane + 32];
            const float4 cx1 = ((const float4*)s_ctx)[lane];
            const float4 cx2 = ((const float4*)s_ctx)[lane + 32];
            for (int rr = 0; rr < nr; rr++) {
                const int lrow = r0 + rr;
                const int row  = OSL * rank + lrow;
                const float4* wo = (const float4*)(W_out + (size_t)row * 512);
                const float4 a0 = wo[lane], a1 = wo[lane + 32];
                const float4 a2 = wo[lane + 64], a3 = wo[lane + 96];
                float acc = a0.x * h1.x + a0.y * h1.y + a0.z * h1.z + a0.w * h1.w
                          + a1.x * h2.x + a1.y * h2.y + a1.z * h2.z + a1.w * h2.w
                          + a2.x * cx1.x + a2.y * cx1.y + a2.z * cx1.z + a2.w * cx1.w
                          + a3.x * cx2.x + a3.y * cx2.y + a3.z * cx2.z + a3.w * cx2.w;
#pragma unroll
                for (int o = 16; o > 0; o >>= 1) acc += __shfl_xor_sync(0xffffffffu, acc, o);
                if (lane == 0) s_logits[lrow] = acc + s_bout[lrow];
            }
        }
        __syncthreads();
        if (w == 24) {
            float lv = (lane < OSL) ? s_logits[lane] : -1e30f;
            float lm = lv;
#pragma unroll
            for (int o = 16; o > 0; o >>= 1) lm = fmaxf(lm, __shfl_xor_sync(0xffffffffu, lm, o));
            float le = (lane < OSL) ? __expf(lv - lm) : 0.f;
#pragma unroll
            for (int o = 16; o > 0; o >>= 1) le += __shfl_xor_sync(0xffffffffu, le, o);
            if (lane == 0) {
#pragma unroll
                for (int p = 0; p < CL; p++) {
                    float* d = clu.map_shared_rank(&s_oms[rank][0], p);
                    d[0] = lm; d[1] = le;
                }
            }
        }
        clu.sync();
        if (w == 31) {
            float M2 = -1e30f;
#pragma unroll
            for (int p = 0; p < CL; p++) M2 = fmaxf(M2, s_oms[p][0]);
            float S2 = 0.f;
#pragma unroll
            for (int p = 0; p < CL; p++) S2 += s_oms[p][1] * __expf(s_oms[p][0] - M2);
            const float off = M2 + __logf(S2);
            if (lane < OSL)
                pred_out[(size_t)(b * T_DEC + (T_DEC - 1)) * IDIM + OSL * rank + lane] =
                    s_logits[lane] - off;
        }
    }
}

// ---------------------------------------------------------------------------
extern "C" void kernel_launch(void* const* d_in, const int* in_sizes, int n_in,
                              void* d_out, int out_size)
{
    const float* enc_feat = (const float*)d_in[0];
    const float* gt       = (const float*)d_in[1];
    const float* W_ih     = (const float*)d_in[2];
    const float* W_hh     = (const float*)d_in[3];
    const float* b_ih     = (const float*)d_in[4];
    const float* b_hh     = (const float*)d_in[5];
    const float* W_enc    = (const float*)d_in[6];
    const float* W_dec    = (const float*)d_in[7];
    const float* b_attn   = (const float*)d_in[8];
    const float* v_attn   = (const float*)d_in[9];
    const float* W_out    = (const float*)d_in[10];
    const float* b_out    = (const float*)d_in[11];

    float* pred = (float*)d_out;                              // (B, T_DEC, 80)
    float* attn = (float*)d_out + (size_t)BB * T_DEC * IDIM;  // (B, T_DEC, 800)

    float* ep_ptr = nullptr;
    float* gx_ptr = nullptr;
    cudaGetSymbolAddress((void**)&ep_ptr, g_enc_proj);
    cudaGetSymbolAddress((void**)&gx_ptr, g_gx);

    static bool attr_set = false;
    if (!attr_set) {
        cudaFuncSetAttribute(decode_kernel,
                             cudaFuncAttributeMaxDynamicSharedMemorySize, SMEM_DYN);
        attr_set = true;
    }

    convert_weights<<<(3 * GDIM * EDIM + 255) / 256, 256>>>(W_ih, W_hh);
    gemm_abt<<<dim3(1, 400), 256>>>(enc_feat, W_enc, ep_ptr,
                                    BB * T_ENC, ADIM, EDIM, EDIM, EDIM, ADIM);
    gemm_abt<<<dim3(6, 200), 256>>>(gt, W_ih, gx_ptr,
                                    BB * T_DEC, 3 * GDIM, IDIM, IDIM, 336, 3 * GDIM);

    decode_kernel<<<BB * CL, 1024, SMEM_DYN>>>(enc_feat, b_ih, b_hh,
                                               W_dec, b_attn, v_attn, W_out, b_out,
                                               pred, attn);
}

// round 12
// speedup vs baseline: 1.0651x; 1.0651x over previous
#include <cuda_runtime.h>
#include <cuda_fp16.h>
#include <cooperative_groups.h>
#include <cstdint>

namespace cg = cooperative_groups;

#define BB 32
#define T_ENC 800
#define T_DEC 400
#define EDIM 256
#define GDIM 256
#define ADIM 128
#define IDIM 80
#define CL 4              // cluster size (CTAs per batch element)
#define GSL (GDIM / CL)   // 64 hidden units per rank
#define ASL (ADIM / CL)   // 32 attn-proj rows per rank
#define TSL (T_ENC / CL)  // 200 encoder steps per rank
#define OSL (IDIM / CL)   // 20 output rows per rank
#define NROWS (3 * GSL)   // 192 GRU rows per rank

// Scratch (allocation-free: __device__ globals)
__device__ __align__(16) float g_enc_proj[BB * T_ENC * ADIM];   // 13.1 MB
__device__ __align__(16) float g_gx[BB * T_DEC * 3 * GDIM];     // 39.3 MB
__device__ __align__(16) __half g_wih_h[3 * GDIM * EDIM];       // fp16 ctx-part of W_ih
__device__ __align__(16) __half g_whh_h[3 * GDIM * GDIM];       // fp16 W_hh

#define SMEM_DYN (2 * NROWS * 256 * (int)sizeof(__half))        // 192 KB

__device__ __forceinline__ float fast_tanh(float x) {
    float y;
    asm("tanh.approx.f32 %0, %1;" : "=f"(y) : "f"(x));
    return y;
}
__device__ __forceinline__ float fast_sig(float x) {
    return 0.5f * fast_tanh(0.5f * x) + 0.5f;
}
__device__ __forceinline__ float warp_sum(float v) {
#pragma unroll
    for (int o = 16; o > 0; o >>= 1) v += __shfl_xor_sync(0xffffffffu, v, o);
    return v;
}
__device__ __forceinline__ float warp_max(float v) {
#pragma unroll
    for (int o = 16; o > 0; o >>= 1) v = fmaxf(v, __shfl_xor_sync(0xffffffffu, v, o));
    return v;
}

// fp16 row-dot: 8 contiguous columns per lane ([lane*8, +8))
__device__ __forceinline__ float dot_row_h(const __half* wrow, int lane,
                                           __half2 x0, __half2 x1,
                                           __half2 x2, __half2 x3)
{
    const uint4 wv = *(const uint4*)(wrow + lane * 8);
    const __half2 w0 = *(const __half2*)&wv.x, w1 = *(const __half2*)&wv.y;
    const __half2 w2 = *(const __half2*)&wv.z, w3 = *(const __half2*)&wv.w;
    __half2 pa = __hfma2(w1, x1, __hmul2(w0, x0));
    __half2 pb = __hfma2(w3, x3, __hmul2(w2, x2));
    const float2 fa = __half22float2(pa), fb = __half22float2(pb);
    return (fa.x + fa.y) + (fb.x + fb.y);
}

// ---------------------------------------------------------------------------
__global__ void convert_weights(const float* __restrict__ W_ih,
                                const float* __restrict__ W_hh)
{
    const int i = blockIdx.x * blockDim.x + threadIdx.x;
    if (i < 3 * GDIM * EDIM) {
        const int r = i >> 8, c = i & 255;
        g_wih_h[i] = __float2half(W_ih[(size_t)r * 336 + 80 + c]);
        g_whh_h[i] = __float2half(W_hh[i]);
    }
}

// ---------------------------------------------------------------------------
// Generic tiled GEMM: C[M,N] = A[M,K] @ B[N,K]^T
// ---------------------------------------------------------------------------
__global__ void gemm_abt(const float* __restrict__ Ap, const float* __restrict__ Bp,
                         float* __restrict__ Cp,
                         int M, int N, int K, int lda, int ldb, int ldc)
{
    __shared__ float As[64][33];
    __shared__ float Bs[128][33];
    const int tb_m = blockIdx.y * 64;
    const int tb_n = blockIdx.x * 128;
    const int tid  = threadIdx.x;
    const int col  = tid & 127;
    const int rg   = tid >> 7;

    float acc[32];
#pragma unroll
    for (int r = 0; r < 32; r++) acc[r] = 0.f;

    for (int k0 = 0; k0 < K; k0 += 32) {
        const int kw = (K - k0 < 32) ? (K - k0) : 32;
        for (int i = tid; i < 64 * 32; i += 256) {
            int r = i >> 5, c = i & 31;
            As[r][c] = (c < kw) ? Ap[(size_t)(tb_m + r) * lda + k0 + c] : 0.f;
        }
        for (int i = tid; i < 128 * 32; i += 256) {
            int r = i >> 5, c = i & 31;
            Bs[r][c] = (c < kw) ? Bp[(size_t)(tb_n + r) * ldb + k0 + c] : 0.f;
        }
        __syncthreads();
#pragma unroll
        for (int kk = 0; kk < 32; kk++) {
            float bv = Bs[col][kk];
#pragma unroll
            for (int r = 0; r < 32; r++)
                acc[r] += As[rg * 32 + r][kk] * bv;
        }
        __syncthreads();
    }
#pragma unroll
    for (int r = 0; r < 32; r++)
        Cp[(size_t)(tb_m + rg * 32 + r) * ldc + tb_n + col] = acc[r];
}

// ---------------------------------------------------------------------------
// Clustered persistent decode (R9 structure, shfl reductions).
//   warps 0-23: GRU-A(t), warps 24-31: E(t-1) (deferred output).
//   3 cluster syncs/step. Phase C ILP-2 unrolled.
// ---------------------------------------------------------------------------
__global__ void __launch_bounds__(1024, 1) __cluster_dims__(CL, 1, 1)
decode_kernel(
    const float* __restrict__ enc_feat,
    const float* __restrict__ b_ih, const float* __restrict__ b_hh,
    const float* __restrict__ W_dec, const float* __restrict__ b_attn,
    const float* __restrict__ v_attn,
    const float* __restrict__ W_out, const float* __restrict__ b_out,
    float* __restrict__ pred_out, float* __restrict__ attn_out)
{
    cg::cluster_group clu = cg::this_cluster();
    const int rank = (int)clu.block_rank();
    const int b    = blockIdx.x / CL;
    const int tid  = threadIdx.x;
    const int lane = tid & 31;
    const int w    = tid >> 5;

    extern __shared__ __align__(16) __half s_wdyn[];
    __half* s_wih = s_wdyn;                 // [NROWS][256]
    __half* s_whh = s_wdyn + NROWS * 256;   // [NROWS][256]

    __shared__ __align__(16) float s_hbuf[2][GDIM];
    __shared__ __align__(16) float s_ctx[EDIM];
    __shared__ __align__(16) __half2 s_hh2[GDIM / 2];
    __shared__ __align__(16) __half2 s_ch2[EDIM / 2];
    __shared__ __align__(16) float s_grz[2 * GSL];
    __shared__ __align__(16) float s_gni[GSL];
    __shared__ __align__(16) float s_gnh[GSL];
    __shared__ __align__(16) float s_gx[NROWS];
    __shared__ __align__(16) float s_brz[2 * GSL];
    __shared__ __align__(16) float s_bni[GSL], s_bnh[GSL];
    __shared__ __align__(16) float s_dp[ADIM];
    __shared__ __align__(16) float s_e[TSL];
    __shared__ __align__(16) float s_ctxp[16][EDIM];
    __shared__ __align__(16) float s_ctxpart[CL][EDIM];
    __shared__ __align__(16) float s_logits[OSL];
    __shared__ float s_bmax, s_bsum;
    __shared__ float s_ms[CL][2];
    __shared__ float s_oms[CL][2];

    // ---- one-time: fp16 weight slice to SMEM ------------------------------
#pragma unroll
    for (int g = 0; g < 3; g++) {
        const uint4* src_i = (const uint4*)(g_wih_h + (size_t)(g * GDIM + GSL * rank) * 256);
        const uint4* src_h = (const uint4*)(g_whh_h + (size_t)(g * GDIM + GSL * rank) * 256);
        uint4* dst_i = (uint4*)(s_wih + (size_t)g * GSL * 256);
        uint4* dst_h = (uint4*)(s_whh + (size_t)g * GSL * 256);
        for (int i = tid; i < GSL * 256 / 8; i += 1024) {
            dst_i[i] = src_i[i];
            dst_h[i] = src_h[i];
        }
    }
    if (tid < GSL) {
        const int u = tid;
#pragma unroll
        for (int g = 0; g < 2; g++) {
            const int row = g * GDIM + GSL * rank + u;
            s_brz[g * GSL + u] = b_ih[row] + b_hh[row];
        }
        const int rown = 2 * GDIM + GSL * rank + u;
        s_bni[u] = b_ih[rown];
        s_bnh[u] = b_hh[rown];
    }
    if (tid < GDIM) s_hbuf[0][tid] = 0.f;
    if (tid < EDIM) s_ctx[tid] = 0.f;
    if (tid < 128) { s_hh2[tid] = __half2half2(__float2half(0.f));
                     s_ch2[tid] = __half2half2(__float2half(0.f)); }
    {
        const float* gx0 = g_gx + (size_t)(b * T_DEC) * 768;
        if (tid < NROWS) {
            const int g = tid / GSL, u = tid % GSL;
            s_gx[tid] = gx0[g * GDIM + GSL * rank + u];
        }
    }
    clu.sync();

    const float4* ep4  = (const float4*)g_enc_proj + (size_t)b * T_ENC * (ADIM / 4);
    const float4* ef4  = (const float4*)enc_feat   + (size_t)b * T_ENC * (EDIM / 4);
    const float4  vreg = ((const float4*)v_attn)[lane];
    const int tbase = TSL * rank;

    for (int t = 0; t < T_DEC; t++) {
        const int cb = t & 1, nb = cb ^ 1;

        // ===== Joint block: GRU-A(t) on warps 0-23, E(t-1) on warps 24-31 ==
        if (w < 24) {
            const __half2 xi0 = s_ch2[lane * 4 + 0], xi1 = s_ch2[lane * 4 + 1];
            const __half2 xi2 = s_ch2[lane * 4 + 2], xi3 = s_ch2[lane * 4 + 3];
            const __half2 xh0 = s_hh2[lane * 4 + 0], xh1 = s_hh2[lane * 4 + 1];
            const __half2 xh2 = s_hh2[lane * 4 + 2], xh3 = s_hh2[lane * 4 + 3];
            const int nu = (w < 16) ? 3 : 2;
#pragma unroll
            for (int j = 0; j < 3; j++) {
                if (j < nu) {
                    const int u = w + 24 * j;   // covers u = 0..63 exactly once
                    float rv = dot_row_h(s_wih + (size_t)u * 256, lane, xi0, xi1, xi2, xi3)
                             + dot_row_h(s_whh + (size_t)u * 256, lane, xh0, xh1, xh2, xh3);
                    float zv = dot_row_h(s_wih + (size_t)(64 + u) * 256, lane, xi0, xi1, xi2, xi3)
                             + dot_row_h(s_whh + (size_t)(64 + u) * 256, lane, xh0, xh1, xh2, xh3);
                    float ni = dot_row_h(s_wih + (size_t)(128 + u) * 256, lane, xi0, xi1, xi2, xi3);
                    float nh = dot_row_h(s_whh + (size_t)(128 + u) * 256, lane, xh0, xh1, xh2, xh3);
#pragma unroll
                    for (int o = 16; o > 0; o >>= 1) {
                        rv += __shfl_xor_sync(0xffffffffu, rv, o);
                        zv += __shfl_xor_sync(0xffffffffu, zv, o);
                        ni += __shfl_xor_sync(0xffffffffu, ni, o);
                        nh += __shfl_xor_sync(0xffffffffu, nh, o);
                    }
                    if (lane == 0) {
                        s_grz[u]        = rv + s_gx[u] + s_brz[u];
                        s_grz[GSL + u]  = zv + s_gx[GSL + u] + s_brz[GSL + u];
                        s_gni[u]        = ni + s_gx[2 * GSL + u] + s_bni[u];
                        s_gnh[u]        = nh + s_bnh[u];
                    }
                }
            }
        } else if (t > 0) {
            // E(t-1): h_{t-1} = s_hbuf[cb], ctx_{t-1} = s_ctx
            const int ew = w - 24;
            const int r0 = (ew < 4) ? ew * 3 : 12 + (ew - 4) * 2;
            const int nr = (ew < 4) ? 3 : 2;
            const float4 h1  = ((const float4*)s_hbuf[cb])[lane];
            const float4 h2  = ((const float4*)s_hbuf[cb])[lane + 32];
            const float4 cx1 = ((const float4*)s_ctx)[lane];
            const float4 cx2 = ((const float4*)s_ctx)[lane + 32];
            for (int rr = 0; rr < nr; rr++) {
                const int lrow = r0 + rr;
                const int row  = OSL * rank + lrow;
                const float4* wo = (const float4*)(W_out + (size_t)row * 512);
                const float4 a0 = wo[lane], a1 = wo[lane + 32];
                const float4 a2 = wo[lane + 64], a3 = wo[lane + 96];
                float acc = a0.x * h1.x + a0.y * h1.y + a0.z * h1.z + a0.w * h1.w
                          + a1.x * h2.x + a1.y * h2.y + a1.z * h2.z + a1.w * h2.w
                          + a2.x * cx1.x + a2.y * cx1.y + a2.z * cx1.z + a2.w * cx1.w
                          + a3.x * cx2.x + a3.y * cx2.y + a3.z * cx2.z + a3.w * cx2.w;
                acc = warp_sum(acc);
                if (lane == 0) s_logits[lrow] = acc + b_out[row];
            }
        }
        __syncthreads();

        // ---- gates -> h_t slice (DSMEM) ; warp 24: oms(t-1) (DSMEM) -------
        if (tid < GSL) {
            const int u = tid;
            const float r = fast_sig(s_grz[u]);
            const float z = fast_sig(s_grz[GSL + u]);
            const float n = fast_tanh(s_gni[u] + r * s_gnh[u]);
            const float hn = (1.f - z) * n + z * s_hbuf[cb][GSL * rank + u];
#pragma unroll
            for (int p = 0; p < CL; p++)
                *clu.map_shared_rank(&s_hbuf[nb][GSL * rank + u], p) = hn;
        }
        if (t > 0 && w == 24) {
            float lv = (lane < OSL) ? s_logits[lane] : -1e30f;
            const float lm = warp_max(lv);
            float le = (lane < OSL) ? __expf(lv - lm) : 0.f;
            le = warp_sum(le);
            if (lane == 0) {
#pragma unroll
                for (int p = 0; p < CL; p++) {
                    float* d = clu.map_shared_rank(&s_oms[rank][0], p);
                    d[0] = lm; d[1] = le;
                }
            }
        }
        clu.sync();   // #1: h_t + oms(t-1) visible everywhere

        // ---- warp 31: write output for t-1 --------------------------------
        if (t > 0 && w == 31) {
            float M2 = -1e30f;
#pragma unroll
            for (int p = 0; p < CL; p++) M2 = fmaxf(M2, s_oms[p][0]);
            float S2 = 0.f;
#pragma unroll
            for (int p = 0; p < CL; p++) S2 += s_oms[p][1] * __expf(s_oms[p][0] - M2);
            const float off = M2 + __logf(S2);
            if (lane < OSL)
                pred_out[(size_t)(b * T_DEC + (t - 1)) * IDIM + OSL * rank + lane] =
                    s_logits[lane] - off;
        }

        // ---- B: dec_proj slice rows [32*rank, +32), broadcast -------------
        {
            const float4 h1 = ((const float4*)s_hbuf[nb])[lane];
            const float4 h2 = ((const float4*)s_hbuf[nb])[lane + 32];
            const int row = ASL * rank + w;
            const float4* wd = (const float4*)(W_dec + (size_t)row * 256);
            const float4 wa = wd[lane], wb = wd[lane + 32];
            float a1 = wa.x * h1.x + wa.y * h1.y + wa.z * h1.z + wa.w * h1.w
                     + wb.x * h2.x + wb.y * h2.y + wb.z * h2.z + wb.w * h2.w;
            a1 = warp_sum(a1);
            if (lane == 0) {
                const float val = a1 + b_attn[row];
#pragma unroll
                for (int p = 0; p < CL; p++)
                    *clu.map_shared_rank(&s_dp[row], p) = val;
            }
        }
        clu.sync();   // #2: full dec_proj visible

        // ---- C: scores for tt in [200*rank, +200), ILP-2 unrolled ---------
        {
            const float4 dpv = ((const float4*)s_dp)[lane];
            for (int tt = w; tt < TSL; tt += 64) {
                const int tt2 = tt + 32;
                const bool has2 = (tt2 < TSL);
                const float4 e1 = ep4[(size_t)(tbase + tt) * 32 + lane];
                float4 e2;
                if (has2) e2 = ep4[(size_t)(tbase + tt2) * 32 + lane];
                float a1 = fast_tanh(e1.x + dpv.x) * vreg.x
                         + fast_tanh(e1.y + dpv.y) * vreg.y
                         + fast_tanh(e1.z + dpv.z) * vreg.z
                         + fast_tanh(e1.w + dpv.w) * vreg.w;
                float a2 = 0.f;
                if (has2)
                    a2 = fast_tanh(e2.x + dpv.x) * vreg.x
                       + fast_tanh(e2.y + dpv.y) * vreg.y
                       + fast_tanh(e2.z + dpv.z) * vreg.z
                       + fast_tanh(e2.w + dpv.w) * vreg.w;
#pragma unroll
                for (int o = 16; o > 0; o >>= 1) {
                    a1 += __shfl_xor_sync(0xffffffffu, a1, o);
                    a2 += __shfl_xor_sync(0xffffffffu, a2, o);
                }
                if (lane == 0) {
                    s_e[tt] = a1;
                    if (has2) s_e[tt2] = a2;
                }
            }
        }
        __syncthreads();

        // ---- softmax stats (200 values): single-warp two-pass -------------
        if (w == 0) {
            float m = -1e30f;
#pragma unroll
            for (int k = 0; k < 7; k++) {
                const int i = lane + 32 * k;
                if (i < TSL) m = fmaxf(m, s_e[i]);
            }
            m = warp_max(m);
            float s = 0.f;
#pragma unroll
            for (int k = 0; k < 7; k++) {
                const int i = lane + 32 * k;
                if (i < TSL) { const float e = __expf(s_e[i] - m); s_e[i] = e; s += e; }
            }
            s = warp_sum(s);
            if (lane == 0) { s_bmax = m; s_bsum = s; }
        }
        __syncthreads();
        const float m_r = s_bmax;

        // ---- D: local ctx partial (unnormalized, local-max weights) -------
        {
            const int q  = tid >> 6;
            const int c4 = tid & 63;
            float4 acc = make_float4(0.f, 0.f, 0.f, 0.f);
            for (int tt = q; tt < TSL; tt += 16) {
                const float wgt = s_e[tt];
                const float4 ev = ef4[(size_t)(tbase + tt) * 64 + c4];
                acc.x += wgt * ev.x; acc.y += wgt * ev.y;
                acc.z += wgt * ev.z; acc.w += wgt * ev.w;
            }
            ((float4*)s_ctxp[q])[c4] = acc;
        }
        __syncthreads();
        if (tid < 64) {
            float4 r4 = make_float4(0.f, 0.f, 0.f, 0.f);
#pragma unroll
            for (int qq = 0; qq < 16; qq++) {
                const float4 p4 = ((const float4*)s_ctxp[qq])[tid];
                r4.x += p4.x; r4.y += p4.y; r4.z += p4.z; r4.w += p4.w;
            }
#pragma unroll
            for (int p = 0; p < CL; p++)
                ((float4*)clu.map_shared_rank(&s_ctxpart[rank][0], p))[tid] = r4;
        }
        if (tid == 0) {
#pragma unroll
            for (int p = 0; p < CL; p++) {
                float* d = clu.map_shared_rank(&s_ms[rank][0], p);
                d[0] = s_bmax; d[1] = s_bsum;
            }
        }
        clu.sync();   // #3: ctx partials + (m,s) pairs visible

        // ---- merge: global softmax + ctx + attn record --------------------
        float M = -1e30f;
#pragma unroll
        for (int p = 0; p < CL; p++) M = fmaxf(M, s_ms[p][0]);
        float S = 0.f;
#pragma unroll
        for (int p = 0; p < CL; p++) S += s_ms[p][1] * __expf(s_ms[p][0] - M);
        const float invS = 1.f / S;
        if (tid < 64) {
            float4 r4 = make_float4(0.f, 0.f, 0.f, 0.f);
#pragma unroll
            for (int p = 0; p < CL; p++) {
                const float wp = __expf(s_ms[p][0] - M);
                const float4 p4 = ((const float4*)&s_ctxpart[p][0])[tid];
                r4.x += wp * p4.x; r4.y += wp * p4.y;
                r4.z += wp * p4.z; r4.w += wp * p4.w;
            }
            r4.x *= invS; r4.y *= invS; r4.z *= invS; r4.w *= invS;
            ((float4*)s_ctx)[tid] = r4;
        }
        {
            const float sc = __expf(m_r - M) * invS;
            if (tid >= 64 && tid < 64 + TSL / 4) {
                const int i = tid - 64;
                float4 e4 = ((const float4*)s_e)[i];
                e4.x *= sc; e4.y *= sc; e4.z *= sc; e4.w *= sc;
                ((float4*)(attn_out + (size_t)(b * T_DEC + t) * T_ENC + tbase))[i] = e4;
            }
        }
        __syncthreads();

        // ---- convert h_t/ctx_t to fp16 + prefetch gx(t+1) -----------------
        if (tid < 128) {
            s_hh2[tid] = __floats2half2_rn(s_hbuf[nb][2 * tid], s_hbuf[nb][2 * tid + 1]);
            s_ch2[tid] = __floats2half2_rn(s_ctx[2 * tid], s_ctx[2 * tid + 1]);
        }
        if (t + 1 < T_DEC && tid >= 128 && tid < 128 + NROWS) {
            const int i = tid - 128;
            const float* gxn = g_gx + (size_t)(b * T_DEC + t + 1) * 768;
            const int g = i / GSL, u = i % GSL;
            s_gx[i] = gxn[g * GDIM + GSL * rank + u];
        }
        __syncthreads();
    }

    // ===== Flush: output phase for final step T_DEC-1 ======================
    {
        const int cbf = T_DEC & 1;   // buffer holding h_{T_DEC-1}
        if (w >= 24) {
            const int ew = w - 24;
            const int r0 = (ew < 4) ? ew * 3 : 12 + (ew - 4) * 2;
            const int nr = (ew < 4) ? 3 : 2;
            const float4 h1  = ((const float4*)s_hbuf[cbf])[lane];
            const float4 h2  = ((const float4*)s_hbuf[cbf])[lane + 32];
            const float4 cx1 = ((const float4*)s_ctx)[lane];
            const float4 cx2 = ((const float4*)s_ctx)[lane + 32];
            for (int rr = 0; rr < nr; rr++) {
                const int lrow = r0 + rr;
                const int row  = OSL * rank + lrow;
                const float4* wo = (const float4*)(W_out + (size_t)row * 512);
                const float4 a0 = wo[lane], a1 = wo[lane + 32];
                const float4 a2 = wo[lane + 64], a3 = wo[lane + 96];
                float acc = a0.x * h1.x + a0.y * h1.y + a0.z * h1.z + a0.w * h1.w
                          + a1.x * h2.x + a1.y * h2.y + a1.z * h2.z + a1.w * h2.w
                          + a2.x * cx1.x + a2.y * cx1.y + a2.z * cx1.z + a2.w * cx1.w
                          + a3.x * cx2.x + a3.y * cx2.y + a3.z * cx2.z + a3.w * cx2.w;
                acc = warp_sum(acc);
                if (lane == 0) s_logits[lrow] = acc + b_out[row];
            }
        }
        __syncthreads();
        if (w == 24) {
            float lv = (lane < OSL) ? s_logits[lane] : -1e30f;
            const float lm = warp_max(lv);
            float le = (lane < OSL) ? __expf(lv - lm) : 0.f;
            le = warp_sum(le);
            if (lane == 0) {
#pragma unroll
                for (int p = 0; p < CL; p++) {
                    float* d = clu.map_shared_rank(&s_oms[rank][0], p);
                    d[0] = lm; d[1] = le;
                }
            }
        }
        clu.sync();
        if (w == 31) {
            float M2 = -1e30f;
#pragma unroll
            for (int p = 0; p < CL; p++) M2 = fmaxf(M2, s_oms[p][0]);
            float S2 = 0.f;
#pragma unroll
            for (int p = 0; p < CL; p++) S2 += s_oms[p][1] * __expf(s_oms[p][0] - M2);
            const float off = M2 + __logf(S2);
            if (lane < OSL)
                pred_out[(size_t)(b * T_DEC + (T_DEC - 1)) * IDIM + OSL * rank + lane] =
                    s_logits[lane] - off;
        }
    }
}

// ---------------------------------------------------------------------------
extern "C" void kernel_launch(void* const* d_in, const int* in_sizes, int n_in,
                              void* d_out, int out_size)
{
    const float* enc_feat = (const float*)d_in[0];
    const float* gt       = (const float*)d_in[1];
    const float* W_ih     = (const float*)d_in[2];
    const float* W_hh     = (const float*)d_in[3];
    const float* b_ih     = (const float*)d_in[4];
    const float* b_hh     = (const float*)d_in[5];
    const float* W_enc    = (const float*)d_in[6];
    const float* W_dec    = (const float*)d_in[7];
    const float* b_attn   = (const float*)d_in[8];
    const float* v_attn   = (const float*)d_in[9];
    const float* W_out    = (const float*)d_in[10];
    const float* b_out    = (const float*)d_in[11];

    float* pred = (float*)d_out;                              // (B, T_DEC, 80)
    float* attn = (float*)d_out + (size_t)BB * T_DEC * IDIM;  // (B, T_DEC, 800)

    float* ep_ptr = nullptr;
    float* gx_ptr = nullptr;
    cudaGetSymbolAddress((void**)&ep_ptr, g_enc_proj);
    cudaGetSymbolAddress((void**)&gx_ptr, g_gx);

    static bool attr_set = false;
    if (!attr_set) {
        cudaFuncSetAttribute(decode_kernel,
                             cudaFuncAttributeMaxDynamicSharedMemorySize, SMEM_DYN);
        attr_set = true;
    }

    convert_weights<<<(3 * GDIM * EDIM + 255) / 256, 256>>>(W_ih, W_hh);
    gemm_abt<<<dim3(1, 400), 256>>>(enc_feat, W_enc, ep_ptr,
                                    BB * T_ENC, ADIM, EDIM, EDIM, EDIM, ADIM);
    gemm_abt<<<dim3(6, 200), 256>>>(gt, W_ih, gx_ptr,
                                    BB * T_DEC, 3 * GDIM, IDIM, IDIM, 336, 3 * GDIM);

    decode_kernel<<<BB * CL, 1024, SMEM_DYN>>>(enc_feat, b_ih, b_hh,
                                               W_dec, b_attn, v_attn, W_out, b_out,
                                               pred, attn);
}

// round 13
// speedup vs baseline: 1.1118x; 1.0438x over previous
#include <cuda_runtime.h>
#include <cuda_fp16.h>
#include <cooperative_groups.h>
#include <cstdint>

namespace cg = cooperative_groups;

#define BB 32
#define T_ENC 800
#define T_DEC 400
#define EDIM 256
#define GDIM 256
#define ADIM 128
#define IDIM 80
#define CL 4              // cluster size (CTAs per batch element)
#define GSL (GDIM / CL)   // 64 hidden units per rank
#define ASL (ADIM / CL)   // 32 attn-proj rows per rank
#define TSL (T_ENC / CL)  // 200 encoder steps per rank
#define OSL (IDIM / CL)   // 20 output rows per rank
#define NROWS (3 * GSL)   // 192 GRU rows per rank

// Scratch (allocation-free: __device__ globals)
__device__ __align__(16) float g_enc_proj[BB * T_ENC * ADIM];   // 13.1 MB
__device__ __align__(16) float g_gx[BB * T_DEC * 3 * GDIM];     // 39.3 MB
__device__ __align__(16) __half g_wih_h[3 * GDIM * EDIM];       // fp16 ctx-part of W_ih
__device__ __align__(16) __half g_whh_h[3 * GDIM * GDIM];       // fp16 W_hh

#define SMEM_DYN (2 * NROWS * 256 * (int)sizeof(__half))        // 192 KB

__device__ __forceinline__ float fast_tanh(float x) {
    float y;
    asm("tanh.approx.f32 %0, %1;" : "=f"(y) : "f"(x));
    return y;
}
__device__ __forceinline__ float fast_sig(float x) {
    return 0.5f * fast_tanh(0.5f * x) + 0.5f;
}
__device__ __forceinline__ float warp_sum(float v) {
#pragma unroll
    for (int o = 16; o > 0; o >>= 1) v += __shfl_xor_sync(0xffffffffu, v, o);
    return v;
}
__device__ __forceinline__ float warp_max(float v) {
#pragma unroll
    for (int o = 16; o > 0; o >>= 1) v = fmaxf(v, __shfl_xor_sync(0xffffffffu, v, o));
    return v;
}

// fp16 row-dot: 8 contiguous columns per lane ([lane*8, +8))
__device__ __forceinline__ float dot_row_h(const __half* wrow, int lane,
                                           __half2 x0, __half2 x1,
                                           __half2 x2, __half2 x3)
{
    const uint4 wv = *(const uint4*)(wrow + lane * 8);
    const __half2 w0 = *(const __half2*)&wv.x, w1 = *(const __half2*)&wv.y;
    const __half2 w2 = *(const __half2*)&wv.z, w3 = *(const __half2*)&wv.w;
    __half2 pa = __hfma2(w1, x1, __hmul2(w0, x0));
    __half2 pb = __hfma2(w3, x3, __hmul2(w2, x2));
    const float2 fa = __half22float2(pa), fb = __half22float2(pb);
    return (fa.x + fa.y) + (fb.x + fb.y);
}

// ---------------------------------------------------------------------------
__global__ void convert_weights(const float* __restrict__ W_ih,
                                const float* __restrict__ W_hh)
{
    const int i = blockIdx.x * blockDim.x + threadIdx.x;
    if (i < 3 * GDIM * EDIM) {
        const int r = i >> 8, c = i & 255;
        g_wih_h[i] = __float2half(W_ih[(size_t)r * 336 + 80 + c]);
        g_whh_h[i] = __float2half(W_hh[i]);
    }
}

// ---------------------------------------------------------------------------
// Generic tiled GEMM: C[M,N] = A[M,K] @ B[N,K]^T
// ---------------------------------------------------------------------------
__global__ void gemm_abt(const float* __restrict__ Ap, const float* __restrict__ Bp,
                         float* __restrict__ Cp,
                         int M, int N, int K, int lda, int ldb, int ldc)
{
    __shared__ float As[64][33];
    __shared__ float Bs[128][33];
    const int tb_m = blockIdx.y * 64;
    const int tb_n = blockIdx.x * 128;
    const int tid  = threadIdx.x;
    const int col  = tid & 127;
    const int rg   = tid >> 7;

    float acc[32];
#pragma unroll
    for (int r = 0; r < 32; r++) acc[r] = 0.f;

    for (int k0 = 0; k0 < K; k0 += 32) {
        const int kw = (K - k0 < 32) ? (K - k0) : 32;
        for (int i = tid; i < 64 * 32; i += 256) {
            int r = i >> 5, c = i & 31;
            As[r][c] = (c < kw) ? Ap[(size_t)(tb_m + r) * lda + k0 + c] : 0.f;
        }
        for (int i = tid; i < 128 * 32; i += 256) {
            int r = i >> 5, c = i & 31;
            Bs[r][c] = (c < kw) ? Bp[(size_t)(tb_n + r) * ldb + k0 + c] : 0.f;
        }
        __syncthreads();
#pragma unroll
        for (int kk = 0; kk < 32; kk++) {
            float bv = Bs[col][kk];
#pragma unroll
            for (int r = 0; r < 32; r++)
                acc[r] += As[rg * 32 + r][kk] * bv;
        }
        __syncthreads();
    }
#pragma unroll
    for (int r = 0; r < 32; r++)
        Cp[(size_t)(tb_m + rg * 32 + r) * ldc + tb_n + col] = acc[r];
}

// ---------------------------------------------------------------------------
// Clustered persistent decode.
//   warps 0-23: GRU-A(t) with FUSED gate nonlinearity + direct DSMEM h write.
//   warps 24-31: E(t-1) (deferred output), ordered by named bar.sync 1.
//   3 cluster syncs/step.
// ---------------------------------------------------------------------------
__global__ void __launch_bounds__(1024, 1) __cluster_dims__(CL, 1, 1)
decode_kernel(
    const float* __restrict__ enc_feat,
    const float* __restrict__ b_ih, const float* __restrict__ b_hh,
    const float* __restrict__ W_dec, const float* __restrict__ b_attn,
    const float* __restrict__ v_attn,
    const float* __restrict__ W_out, const float* __restrict__ b_out,
    float* __restrict__ pred_out, float* __restrict__ attn_out)
{
    cg::cluster_group clu = cg::this_cluster();
    const int rank = (int)clu.block_rank();
    const int b    = blockIdx.x / CL;
    const int tid  = threadIdx.x;
    const int lane = tid & 31;
    const int w    = tid >> 5;

    extern __shared__ __align__(16) __half s_wdyn[];
    __half* s_wih = s_wdyn;                 // [NROWS][256]
    __half* s_whh = s_wdyn + NROWS * 256;   // [NROWS][256]

    __shared__ __align__(16) float s_hbuf[2][GDIM];
    __shared__ __align__(16) float s_ctx[EDIM];
    __shared__ __align__(16) __half2 s_hh2[GDIM / 2];
    __shared__ __align__(16) __half2 s_ch2[EDIM / 2];
    __shared__ __align__(16) float s_gx[NROWS];
    __shared__ __align__(16) float s_brz[2 * GSL];
    __shared__ __align__(16) float s_bni[GSL], s_bnh[GSL];
    __shared__ __align__(16) float s_dp[ADIM];
    __shared__ __align__(16) float s_e[TSL];
    __shared__ __align__(16) float s_ctxp[16][EDIM];
    __shared__ __align__(16) float s_ctxpart[CL][EDIM];
    __shared__ __align__(16) float s_logits[OSL];
    __shared__ float s_bmax, s_bsum;
    __shared__ float s_ms[CL][2];
    __shared__ float s_oms[CL][2];

    // ---- one-time: fp16 weight slice to SMEM ------------------------------
#pragma unroll
    for (int g = 0; g < 3; g++) {
        const uint4* src_i = (const uint4*)(g_wih_h + (size_t)(g * GDIM + GSL * rank) * 256);
        const uint4* src_h = (const uint4*)(g_whh_h + (size_t)(g * GDIM + GSL * rank) * 256);
        uint4* dst_i = (uint4*)(s_wih + (size_t)g * GSL * 256);
        uint4* dst_h = (uint4*)(s_whh + (size_t)g * GSL * 256);
        for (int i = tid; i < GSL * 256 / 8; i += 1024) {
            dst_i[i] = src_i[i];
            dst_h[i] = src_h[i];
        }
    }
    if (tid < GSL) {
        const int u = tid;
#pragma unroll
        for (int g = 0; g < 2; g++) {
            const int row = g * GDIM + GSL * rank + u;
            s_brz[g * GSL + u] = b_ih[row] + b_hh[row];
        }
        const int rown = 2 * GDIM + GSL * rank + u;
        s_bni[u] = b_ih[rown];
        s_bnh[u] = b_hh[rown];
    }
    if (tid < GDIM) s_hbuf[0][tid] = 0.f;
    if (tid < EDIM) s_ctx[tid] = 0.f;
    if (tid < 128) { s_hh2[tid] = __half2half2(__float2half(0.f));
                     s_ch2[tid] = __half2half2(__float2half(0.f)); }
    {
        const float* gx0 = g_gx + (size_t)(b * T_DEC) * 768;
        if (tid < NROWS) {
            const int g = tid / GSL, u = tid % GSL;
            s_gx[tid] = gx0[g * GDIM + GSL * rank + u];
        }
    }
    clu.sync();

    const float4* ep4  = (const float4*)g_enc_proj + (size_t)b * T_ENC * (ADIM / 4);
    const float4* ef4  = (const float4*)enc_feat   + (size_t)b * T_ENC * (EDIM / 4);
    const float4  vreg = ((const float4*)v_attn)[lane];
    const int tbase = TSL * rank;

    for (int t = 0; t < T_DEC; t++) {
        const int cb = t & 1, nb = cb ^ 1;

        // ===== Joint block =================================================
        if (w < 24) {
            // GRU-A(t) with fused gates: each warp fully owns its units.
            const __half2 xi0 = s_ch2[lane * 4 + 0], xi1 = s_ch2[lane * 4 + 1];
            const __half2 xi2 = s_ch2[lane * 4 + 2], xi3 = s_ch2[lane * 4 + 3];
            const __half2 xh0 = s_hh2[lane * 4 + 0], xh1 = s_hh2[lane * 4 + 1];
            const __half2 xh2 = s_hh2[lane * 4 + 2], xh3 = s_hh2[lane * 4 + 3];
            const int nu = (w < 16) ? 3 : 2;
#pragma unroll
            for (int j = 0; j < 3; j++) {
                if (j < nu) {
                    const int u = w + 24 * j;   // covers u = 0..63 exactly once
                    float rv = dot_row_h(s_wih + (size_t)u * 256, lane, xi0, xi1, xi2, xi3)
                             + dot_row_h(s_whh + (size_t)u * 256, lane, xh0, xh1, xh2, xh3);
                    float zv = dot_row_h(s_wih + (size_t)(64 + u) * 256, lane, xi0, xi1, xi2, xi3)
                             + dot_row_h(s_whh + (size_t)(64 + u) * 256, lane, xh0, xh1, xh2, xh3);
                    float ni = dot_row_h(s_wih + (size_t)(128 + u) * 256, lane, xi0, xi1, xi2, xi3);
                    float nh = dot_row_h(s_whh + (size_t)(128 + u) * 256, lane, xh0, xh1, xh2, xh3);
#pragma unroll
                    for (int o = 16; o > 0; o >>= 1) {
                        rv += __shfl_xor_sync(0xffffffffu, rv, o);
                        zv += __shfl_xor_sync(0xffffffffu, zv, o);
                        ni += __shfl_xor_sync(0xffffffffu, ni, o);
                        nh += __shfl_xor_sync(0xffffffffu, nh, o);
                    }
                    // all lanes hold the sums; fuse gate nonlinearity here
                    const float r  = fast_sig(rv + s_gx[u] + s_brz[u]);
                    const float z  = fast_sig(zv + s_gx[GSL + u] + s_brz[GSL + u]);
                    const float n  = fast_tanh(ni + s_gx[2 * GSL + u] + s_bni[u]
                                               + r * (nh + s_bnh[u]));
                    const float hn = (1.f - z) * n + z * s_hbuf[cb][GSL * rank + u];
                    if (lane < CL)
                        *clu.map_shared_rank(&s_hbuf[nb][GSL * rank + u], lane) = hn;
                }
            }
        } else {
            if (t > 0) {
                // E(t-1): h_{t-1} = s_hbuf[cb], ctx_{t-1} = s_ctx
                const int ew = w - 24;
                const int r0 = (ew < 4) ? ew * 3 : 12 + (ew - 4) * 2;
                const int nr = (ew < 4) ? 3 : 2;
                const float4 h1  = ((const float4*)s_hbuf[cb])[lane];
                const float4 h2  = ((const float4*)s_hbuf[cb])[lane + 32];
                const float4 cx1 = ((const float4*)s_ctx)[lane];
                const float4 cx2 = ((const float4*)s_ctx)[lane + 32];
                for (int rr = 0; rr < nr; rr++) {
                    const int lrow = r0 + rr;
                    const int row  = OSL * rank + lrow;
                    const float4* wo = (const float4*)(W_out + (size_t)row * 512);
                    const float4 a0 = wo[lane], a1 = wo[lane + 32];
                    const float4 a2 = wo[lane + 64], a3 = wo[lane + 96];
                    float acc = a0.x * h1.x + a0.y * h1.y + a0.z * h1.z + a0.w * h1.w
                              + a1.x * h2.x + a1.y * h2.y + a1.z * h2.z + a1.w * h2.w
                              + a2.x * cx1.x + a2.y * cx1.y + a2.z * cx1.z + a2.w * cx1.w
                              + a3.x * cx2.x + a3.y * cx2.y + a3.z * cx2.z + a3.w * cx2.w;
                    acc = warp_sum(acc);
                    if (lane == 0) s_logits[lrow] = acc + b_out[row];
                }
            }
            // order E-warp s_logits stores before warp 24's read (warps 24-31 only)
            asm volatile("bar.sync 1, 256;" ::: "memory");
            if (t > 0 && w == 24) {
                float lv = (lane < OSL) ? s_logits[lane] : -1e30f;
                const float lm = warp_max(lv);
                float le = (lane < OSL) ? __expf(lv - lm) : 0.f;
                le = warp_sum(le);
                if (lane == 0) {
#pragma unroll
                    for (int p = 0; p < CL; p++) {
                        float* d = clu.map_shared_rank(&s_oms[rank][0], p);
                        d[0] = lm; d[1] = le;
                    }
                }
            }
        }
        clu.sync();   // #1: h_t + oms(t-1) visible everywhere

        // ---- warp 31: write output for t-1 --------------------------------
        if (t > 0 && w == 31) {
            float M2 = -1e30f;
#pragma unroll
            for (int p = 0; p < CL; p++) M2 = fmaxf(M2, s_oms[p][0]);
            float S2 = 0.f;
#pragma unroll
            for (int p = 0; p < CL; p++) S2 += s_oms[p][1] * __expf(s_oms[p][0] - M2);
            const float off = M2 + __logf(S2);
            if (lane < OSL)
                pred_out[(size_t)(b * T_DEC + (t - 1)) * IDIM + OSL * rank + lane] =
                    s_logits[lane] - off;
        }

        // ---- B: dec_proj slice rows [32*rank, +32), broadcast -------------
        {
            const float4 h1 = ((const float4*)s_hbuf[nb])[lane];
            const float4 h2 = ((const float4*)s_hbuf[nb])[lane + 32];
            const int row = ASL * rank + w;
            const float4* wd = (const float4*)(W_dec + (size_t)row * 256);
            const float4 wa = wd[lane], wb = wd[lane + 32];
            float a1 = wa.x * h1.x + wa.y * h1.y + wa.z * h1.z + wa.w * h1.w
                     + wb.x * h2.x + wb.y * h2.y + wb.z * h2.z + wb.w * h2.w;
            a1 = warp_sum(a1);
            if (lane == 0) {
                const float val = a1 + b_attn[row];
#pragma unroll
                for (int p = 0; p < CL; p++)
                    *clu.map_shared_rank(&s_dp[row], p) = val;
            }
        }
        clu.sync();   // #2: full dec_proj visible

        // ---- C: scores for tt in [200*rank, +200), ILP-2 unrolled ---------
        {
            const float4 dpv = ((const float4*)s_dp)[lane];
            for (int tt = w; tt < TSL; tt += 64) {
                const int tt2 = tt + 32;
                const bool has2 = (tt2 < TSL);
                const float4 e1 = ep4[(size_t)(tbase + tt) * 32 + lane];
                float4 e2;
                if (has2) e2 = ep4[(size_t)(tbase + tt2) * 32 + lane];
                float a1 = fast_tanh(e1.x + dpv.x) * vreg.x
                         + fast_tanh(e1.y + dpv.y) * vreg.y
                         + fast_tanh(e1.z + dpv.z) * vreg.z
                         + fast_tanh(e1.w + dpv.w) * vreg.w;
                float a2 = 0.f;
                if (has2)
                    a2 = fast_tanh(e2.x + dpv.x) * vreg.x
                       + fast_tanh(e2.y + dpv.y) * vreg.y
                       + fast_tanh(e2.z + dpv.z) * vreg.z
                       + fast_tanh(e2.w + dpv.w) * vreg.w;
#pragma unroll
                for (int o = 16; o > 0; o >>= 1) {
                    a1 += __shfl_xor_sync(0xffffffffu, a1, o);
                    a2 += __shfl_xor_sync(0xffffffffu, a2, o);
                }
                if (lane == 0) {
                    s_e[tt] = a1;
                    if (has2) s_e[tt2] = a2;
                }
            }
        }
        __syncthreads();

        // ---- softmax stats (200 values): single-warp two-pass -------------
        if (w == 0) {
            float m = -1e30f;
#pragma unroll
            for (int k = 0; k < 7; k++) {
                const int i = lane + 32 * k;
                if (i < TSL) m = fmaxf(m, s_e[i]);
            }
            m = warp_max(m);
            float s = 0.f;
#pragma unroll
            for (int k = 0; k < 7; k++) {
                const int i = lane + 32 * k;
                if (i < TSL) { const float e = __expf(s_e[i] - m); s_e[i] = e; s += e; }
            }
            s = warp_sum(s);
            if (lane == 0) { s_bmax = m; s_bsum = s; }
        }
        __syncthreads();
        const float m_r = s_bmax;

        // ---- D: local ctx partial (unnormalized, local-max weights) -------
        {
            const int q  = tid >> 6;
            const int c4 = tid & 63;
            float4 acc = make_float4(0.f, 0.f, 0.f, 0.f);
            for (int tt = q; tt < TSL; tt += 16) {
                const float wgt = s_e[tt];
                const float4 ev = ef4[(size_t)(tbase + tt) * 64 + c4];
                acc.x += wgt * ev.x; acc.y += wgt * ev.y;
                acc.z += wgt * ev.z; acc.w += wgt * ev.w;
            }
            ((float4*)s_ctxp[q])[c4] = acc;
        }
        __syncthreads();
        if (tid < 64) {
            float4 r4 = make_float4(0.f, 0.f, 0.f, 0.f);
#pragma unroll
            for (int qq = 0; qq < 16; qq++) {
                const float4 p4 = ((const float4*)s_ctxp[qq])[tid];
                r4.x += p4.x; r4.y += p4.y; r4.z += p4.z; r4.w += p4.w;
            }
#pragma unroll
            for (int p = 0; p < CL; p++)
                ((float4*)clu.map_shared_rank(&s_ctxpart[rank][0], p))[tid] = r4;
        }
        if (tid == 0) {
#pragma unroll
            for (int p = 0; p < CL; p++) {
                float* d = clu.map_shared_rank(&s_ms[rank][0], p);
                d[0] = s_bmax; d[1] = s_bsum;
            }
        }
        clu.sync();   // #3: ctx partials + (m,s) pairs visible

        // ---- merge: global softmax + ctx + attn record --------------------
        float M = -1e30f;
#pragma unroll
        for (int p = 0; p < CL; p++) M = fmaxf(M, s_ms[p][0]);
        float S = 0.f;
#pragma unroll
        for (int p = 0; p < CL; p++) S += s_ms[p][1] * __expf(s_ms[p][0] - M);
        const float invS = 1.f / S;
        if (tid < 64) {
            float4 r4 = make_float4(0.f, 0.f, 0.f, 0.f);
#pragma unroll
            for (int p = 0; p < CL; p++) {
                const float wp = __expf(s_ms[p][0] - M);
                const float4 p4 = ((const float4*)&s_ctxpart[p][0])[tid];
                r4.x += wp * p4.x; r4.y += wp * p4.y;
                r4.z += wp * p4.z; r4.w += wp * p4.w;
            }
            r4.x *= invS; r4.y *= invS; r4.z *= invS; r4.w *= invS;
            ((float4*)s_ctx)[tid] = r4;
        }
        {
            const float sc = __expf(m_r - M) * invS;
            if (tid >= 64 && tid < 64 + TSL / 4) {
                const int i = tid - 64;
                float4 e4 = ((const float4*)s_e)[i];
                e4.x *= sc; e4.y *= sc; e4.z *= sc; e4.w *= sc;
                ((float4*)(attn_out + (size_t)(b * T_DEC + t) * T_ENC + tbase))[i] = e4;
            }
        }
        __syncthreads();

        // ---- convert h_t/ctx_t to fp16 + prefetch gx(t+1) -----------------
        if (tid < 128) {
            s_hh2[tid] = __floats2half2_rn(s_hbuf[nb][2 * tid], s_hbuf[nb][2 * tid + 1]);
            s_ch2[tid] = __floats2half2_rn(s_ctx[2 * tid], s_ctx[2 * tid + 1]);
        }
        if (t + 1 < T_DEC && tid >= 128 && tid < 128 + NROWS) {
            const int i = tid - 128;
            const float* gxn = g_gx + (size_t)(b * T_DEC + t + 1) * 768;
            const int g = i / GSL, u = i % GSL;
            s_gx[i] = gxn[g * GDIM + GSL * rank + u];
        }
        __syncthreads();
    }

    // ===== Flush: output phase for final step T_DEC-1 ======================
    {
        const int cbf = T_DEC & 1;   // buffer holding h_{T_DEC-1}
        if (w >= 24) {
            const int ew = w - 24;
            const int r0 = (ew < 4) ? ew * 3 : 12 + (ew - 4) * 2;
            const int nr = (ew < 4) ? 3 : 2;
            const float4 h1  = ((const float4*)s_hbuf[cbf])[lane];
            const float4 h2  = ((const float4*)s_hbuf[cbf])[lane + 32];
            const float4 cx1 = ((const float4*)s_ctx)[lane];
            const float4 cx2 = ((const float4*)s_ctx)[lane + 32];
            for (int rr = 0; rr < nr; rr++) {
                const int lrow = r0 + rr;
                const int row  = OSL * rank + lrow;
                const float4* wo = (const float4*)(W_out + (size_t)row * 512);
                const float4 a0 = wo[lane], a1 = wo[lane + 32];
                const float4 a2 = wo[lane + 64], a3 = wo[lane + 96];
                float acc = a0.x * h1.x + a0.y * h1.y + a0.z * h1.z + a0.w * h1.w
                          + a1.x * h2.x + a1.y * h2.y + a1.z * h2.z + a1.w * h2.w
                          + a2.x * cx1.x + a2.y * cx1.y + a2.z * cx1.z + a2.w * cx1.w
                          + a3.x * cx2.x + a3.y * cx2.y + a3.z * cx2.z + a3.w * cx2.w;
                acc = warp_sum(acc);
                if (lane == 0) s_logits[lrow] = acc + b_out[row];
            }
        }
        __syncthreads();
        if (w == 24) {
            float lv = (lane < OSL) ? s_logits[lane] : -1e30f;
            const float lm = warp_max(lv);
            float le = (lane < OSL) ? __expf(lv - lm) : 0.f;
            le = warp_sum(le);
            if (lane == 0) {
#pragma unroll
                for (int p = 0; p < CL; p++) {
                    float* d = clu.map_shared_rank(&s_oms[rank][0], p);
                    d[0] = lm; d[1] = le;
                }
            }
        }
        clu.sync();
        if (w == 31) {
            float M2 = -1e30f;
#pragma unroll
            for (int p = 0; p < CL; p++) M2 = fmaxf(M2, s_oms[p][0]);
            float S2 = 0.f;
#pragma unroll
            for (int p = 0; p < CL; p++) S2 += s_oms[p][1] * __expf(s_oms[p][0] - M2);
            const float off = M2 + __logf(S2);
            if (lane < OSL)
                pred_out[(size_t)(b * T_DEC + (T_DEC - 1)) * IDIM + OSL * rank + lane] =
                    s_logits[lane] - off;
        }
    }
}

// ---------------------------------------------------------------------------
extern "C" void kernel_launch(void* const* d_in, const int* in_sizes, int n_in,
                              void* d_out, int out_size)
{
    const float* enc_feat = (const float*)d_in[0];
    const float* gt       = (const float*)d_in[1];
    const float* W_ih     = (const float*)d_in[2];
    const float* W_hh     = (const float*)d_in[3];
    const float* b_ih     = (const float*)d_in[4];
    const float* b_hh     = (const float*)d_in[5];
    const float* W_enc    = (const float*)d_in[6];
    const float* W_dec    = (const float*)d_in[7];
    const float* b_attn   = (const float*)d_in[8];
    const float* v_attn   = (const float*)d_in[9];
    const float* W_out    = (const float*)d_in[10];
    const float* b_out    = (const float*)d_in[11];

    float* pred = (float*)d_out;                              // (B, T_DEC, 80)
    float* attn = (float*)d_out + (size_t)BB * T_DEC * IDIM;  // (B, T_DEC, 800)

    float* ep_ptr = nullptr;
    float* gx_ptr = nullptr;
    cudaGetSymbolAddress((void**)&ep_ptr, g_enc_proj);
    cudaGetSymbolAddress((void**)&gx_ptr, g_gx);

    static bool attr_set = false;
    if (!attr_set) {
        cudaFuncSetAttribute(decode_kernel,
                             cudaFuncAttributeMaxDynamicSharedMemorySize, SMEM_DYN);
        attr_set = true;
    }

    convert_weights<<<(3 * GDIM * EDIM + 255) / 256, 256>>>(W_ih, W_hh);
    gemm_abt<<<dim3(1, 400), 256>>>(enc_feat, W_enc, ep_ptr,
                                    BB * T_ENC, ADIM, EDIM, EDIM, EDIM, ADIM);
    gemm_abt<<<dim3(6, 200), 256>>>(gt, W_ih, gx_ptr,
                                    BB * T_DEC, 3 * GDIM, IDIM, IDIM, 336, 3 * GDIM);

    decode_kernel<<<BB * CL, 1024, SMEM_DYN>>>(enc_feat, b_ih, b_hh,
                                               W_dec, b_attn, v_attn, W_out, b_out,
                                               pred, attn);
}

// round 14
// speedup vs baseline: 1.1696x; 1.0520x over previous
#include <cuda_runtime.h>
#include <cuda_fp16.h>
#include <cooperative_groups.h>
#include <cstdint>

namespace cg = cooperative_groups;

#define BB 32
#define T_ENC 800
#define T_DEC 400
#define EDIM 256
#define GDIM 256
#define ADIM 128
#define IDIM 80
#define CL 4              // cluster size (CTAs per batch element)
#define GSL (GDIM / CL)   // 64 hidden units per rank
#define ASL (ADIM / CL)   // 32 attn-proj rows per rank
#define TSL (T_ENC / CL)  // 200 encoder steps per rank
#define OSL (IDIM / CL)   // 20 output rows per rank
#define NROWS (3 * GSL)   // 192 GRU rows per rank

// Scratch (allocation-free: __device__ globals)
__device__ __align__(16) float g_enc_proj[BB * T_ENC * ADIM];   // 13.1 MB
__device__ __align__(16) float g_gx[BB * T_DEC * 3 * GDIM];     // 39.3 MB
__device__ __align__(16) __half g_wih_h[3 * GDIM * EDIM];       // fp16 ctx-part of W_ih
__device__ __align__(16) __half g_whh_h[3 * GDIM * GDIM];       // fp16 W_hh

#define SMEM_DYN (2 * NROWS * 256 * (int)sizeof(__half))        // 192 KB

__device__ __forceinline__ float fast_tanh(float x) {
    float y;
    asm("tanh.approx.f32 %0, %1;" : "=f"(y) : "f"(x));
    return y;
}
__device__ __forceinline__ float fast_sig(float x) {
    return 0.5f * fast_tanh(0.5f * x) + 0.5f;
}
__device__ __forceinline__ float warp_sum(float v) {
#pragma unroll
    for (int o = 16; o > 0; o >>= 1) v += __shfl_xor_sync(0xffffffffu, v, o);
    return v;
}
__device__ __forceinline__ float warp_max(float v) {
#pragma unroll
    for (int o = 16; o > 0; o >>= 1) v = fmaxf(v, __shfl_xor_sync(0xffffffffu, v, o));
    return v;
}

// fp16 row-dot: 8 contiguous columns per lane ([lane*8, +8))
__device__ __forceinline__ float dot_row_h(const __half* wrow, int lane,
                                           __half2 x0, __half2 x1,
                                           __half2 x2, __half2 x3)
{
    const uint4 wv = *(const uint4*)(wrow + lane * 8);
    const __half2 w0 = *(const __half2*)&wv.x, w1 = *(const __half2*)&wv.y;
    const __half2 w2 = *(const __half2*)&wv.z, w3 = *(const __half2*)&wv.w;
    __half2 pa = __hfma2(w1, x1, __hmul2(w0, x0));
    __half2 pb = __hfma2(w3, x3, __hmul2(w2, x2));
    const float2 fa = __half22float2(pa), fb = __half22float2(pb);
    return (fa.x + fa.y) + (fb.x + fb.y);
}

// ---------------------------------------------------------------------------
__global__ void convert_weights(const float* __restrict__ W_ih,
                                const float* __restrict__ W_hh)
{
    const int i = blockIdx.x * blockDim.x + threadIdx.x;
    if (i < 3 * GDIM * EDIM) {
        const int r = i >> 8, c = i & 255;
        g_wih_h[i] = __float2half(W_ih[(size_t)r * 336 + 80 + c]);
        g_whh_h[i] = __float2half(W_hh[i]);
    }
}

// ---------------------------------------------------------------------------
// Generic tiled GEMM: C[M,N] = A[M,K] @ B[N,K]^T
// ---------------------------------------------------------------------------
__global__ void gemm_abt(const float* __restrict__ Ap, const float* __restrict__ Bp,
                         float* __restrict__ Cp,
                         int M, int N, int K, int lda, int ldb, int ldc)
{
    __shared__ float As[64][33];
    __shared__ float Bs[128][33];
    const int tb_m = blockIdx.y * 64;
    const int tb_n = blockIdx.x * 128;
    const int tid  = threadIdx.x;
    const int col  = tid & 127;
    const int rg   = tid >> 7;

    float acc[32];
#pragma unroll
    for (int r = 0; r < 32; r++) acc[r] = 0.f;

    for (int k0 = 0; k0 < K; k0 += 32) {
        const int kw = (K - k0 < 32) ? (K - k0) : 32;
        for (int i = tid; i < 64 * 32; i += 256) {
            int r = i >> 5, c = i & 31;
            As[r][c] = (c < kw) ? Ap[(size_t)(tb_m + r) * lda + k0 + c] : 0.f;
        }
        for (int i = tid; i < 128 * 32; i += 256) {
            int r = i >> 5, c = i & 31;
            Bs[r][c] = (c < kw) ? Bp[(size_t)(tb_n + r) * ldb + k0 + c] : 0.f;
        }
        __syncthreads();
#pragma unroll
        for (int kk = 0; kk < 32; kk++) {
            float bv = Bs[col][kk];
#pragma unroll
            for (int r = 0; r < 32; r++)
                acc[r] += As[rg * 32 + r][kk] * bv;
        }
        __syncthreads();
    }
#pragma unroll
    for (int r = 0; r < 32; r++)
        Cp[(size_t)(tb_m + rg * 32 + r) * ldc + tb_n + col] = acc[r];
}

// ---------------------------------------------------------------------------
// Clustered persistent decode.
//   warps 0-23: GRU-A(t) fused gates + direct DSMEM h write.
//   warps 24-31: E(t-1) (deferred output), ordered by named bar.sync 1.
//   Phase C stores exp(score) directly (scores bounded, no max shift).
//   3 cluster syncs/step.
// ---------------------------------------------------------------------------
__global__ void __launch_bounds__(1024, 1) __cluster_dims__(CL, 1, 1)
decode_kernel(
    const float* __restrict__ enc_feat,
    const float* __restrict__ b_ih, const float* __restrict__ b_hh,
    const float* __restrict__ W_dec, const float* __restrict__ b_attn,
    const float* __restrict__ v_attn,
    const float* __restrict__ W_out, const float* __restrict__ b_out,
    float* __restrict__ pred_out, float* __restrict__ attn_out)
{
    cg::cluster_group clu = cg::this_cluster();
    const int rank = (int)clu.block_rank();
    const int b    = blockIdx.x / CL;
    const int tid  = threadIdx.x;
    const int lane = tid & 31;
    const int w    = tid >> 5;

    extern __shared__ __align__(16) __half s_wdyn[];
    __half* s_wih = s_wdyn;                 // [NROWS][256]
    __half* s_whh = s_wdyn + NROWS * 256;   // [NROWS][256]

    __shared__ __align__(16) float s_hbuf[2][GDIM];
    __shared__ __align__(16) float s_ctx[EDIM];
    __shared__ __align__(16) __half2 s_hh2[GDIM / 2];
    __shared__ __align__(16) __half2 s_ch2[EDIM / 2];
    __shared__ __align__(16) float s_gx[NROWS];
    __shared__ __align__(16) float s_brz[2 * GSL];
    __shared__ __align__(16) float s_bni[GSL], s_bnh[GSL];
    __shared__ __align__(16) float s_dp[ADIM];
    __shared__ __align__(16) float s_e[TSL];
    __shared__ __align__(16) float s_ctxp[16][EDIM];
    __shared__ __align__(16) float s_ctxpart[CL][EDIM];
    __shared__ __align__(16) float s_logits[OSL];
    __shared__ float s_bsum;
    __shared__ float s_ms[CL];                          // per-rank exp-sums
    __shared__ float s_oms[CL][2];

    // ---- one-time: fp16 weight slice to SMEM ------------------------------
#pragma unroll
    for (int g = 0; g < 3; g++) {
        const uint4* src_i = (const uint4*)(g_wih_h + (size_t)(g * GDIM + GSL * rank) * 256);
        const uint4* src_h = (const uint4*)(g_whh_h + (size_t)(g * GDIM + GSL * rank) * 256);
        uint4* dst_i = (uint4*)(s_wih + (size_t)g * GSL * 256);
        uint4* dst_h = (uint4*)(s_whh + (size_t)g * GSL * 256);
        for (int i = tid; i < GSL * 256 / 8; i += 1024) {
            dst_i[i] = src_i[i];
            dst_h[i] = src_h[i];
        }
    }
    if (tid < GSL) {
        const int u = tid;
#pragma unroll
        for (int g = 0; g < 2; g++) {
            const int row = g * GDIM + GSL * rank + u;
            s_brz[g * GSL + u] = b_ih[row] + b_hh[row];
        }
        const int rown = 2 * GDIM + GSL * rank + u;
        s_bni[u] = b_ih[rown];
        s_bnh[u] = b_hh[rown];
    }
    if (tid < GDIM) s_hbuf[0][tid] = 0.f;
    if (tid < EDIM) s_ctx[tid] = 0.f;
    if (tid < 128) { s_hh2[tid] = __half2half2(__float2half(0.f));
                     s_ch2[tid] = __half2half2(__float2half(0.f)); }
    {
        const float* gx0 = g_gx + (size_t)(b * T_DEC) * 768;
        if (tid < NROWS) {
            const int g = tid / GSL, u = tid % GSL;
            s_gx[tid] = gx0[g * GDIM + GSL * rank + u];
        }
    }
    clu.sync();

    const float4* ep4  = (const float4*)g_enc_proj + (size_t)b * T_ENC * (ADIM / 4);
    const float4* ef4  = (const float4*)enc_feat   + (size_t)b * T_ENC * (EDIM / 4);
    const float4  vreg = ((const float4*)v_attn)[lane];
    const int tbase = TSL * rank;

    for (int t = 0; t < T_DEC; t++) {
        const int cb = t & 1, nb = cb ^ 1;

        // ===== Joint block =================================================
        if (w < 24) {
            // GRU-A(t) with fused gates: each warp fully owns its units.
            const __half2 xi0 = s_ch2[lane * 4 + 0], xi1 = s_ch2[lane * 4 + 1];
            const __half2 xi2 = s_ch2[lane * 4 + 2], xi3 = s_ch2[lane * 4 + 3];
            const __half2 xh0 = s_hh2[lane * 4 + 0], xh1 = s_hh2[lane * 4 + 1];
            const __half2 xh2 = s_hh2[lane * 4 + 2], xh3 = s_hh2[lane * 4 + 3];
            const int nu = (w < 16) ? 3 : 2;
#pragma unroll
            for (int j = 0; j < 3; j++) {
                if (j < nu) {
                    const int u = w + 24 * j;   // covers u = 0..63 exactly once
                    float rv = dot_row_h(s_wih + (size_t)u * 256, lane, xi0, xi1, xi2, xi3)
                             + dot_row_h(s_whh + (size_t)u * 256, lane, xh0, xh1, xh2, xh3);
                    float zv = dot_row_h(s_wih + (size_t)(64 + u) * 256, lane, xi0, xi1, xi2, xi3)
                             + dot_row_h(s_whh + (size_t)(64 + u) * 256, lane, xh0, xh1, xh2, xh3);
                    float ni = dot_row_h(s_wih + (size_t)(128 + u) * 256, lane, xi0, xi1, xi2, xi3);
                    float nh = dot_row_h(s_whh + (size_t)(128 + u) * 256, lane, xh0, xh1, xh2, xh3);
#pragma unroll
                    for (int o = 16; o > 0; o >>= 1) {
                        rv += __shfl_xor_sync(0xffffffffu, rv, o);
                        zv += __shfl_xor_sync(0xffffffffu, zv, o);
                        ni += __shfl_xor_sync(0xffffffffu, ni, o);
                        nh += __shfl_xor_sync(0xffffffffu, nh, o);
                    }
                    // all lanes hold the sums; fuse gate nonlinearity here
                    const float r  = fast_sig(rv + s_gx[u] + s_brz[u]);
                    const float z  = fast_sig(zv + s_gx[GSL + u] + s_brz[GSL + u]);
                    const float n  = fast_tanh(ni + s_gx[2 * GSL + u] + s_bni[u]
                                               + r * (nh + s_bnh[u]));
                    const float hn = (1.f - z) * n + z * s_hbuf[cb][GSL * rank + u];
                    if (lane < CL)
                        *clu.map_shared_rank(&s_hbuf[nb][GSL * rank + u], lane) = hn;
                }
            }
        } else {
            if (t > 0) {
                // E(t-1): h_{t-1} = s_hbuf[cb], ctx_{t-1} = s_ctx
                const int ew = w - 24;
                const int r0 = (ew < 4) ? ew * 3 : 12 + (ew - 4) * 2;
                const int nr = (ew < 4) ? 3 : 2;
                const float4 h1  = ((const float4*)s_hbuf[cb])[lane];
                const float4 h2  = ((const float4*)s_hbuf[cb])[lane + 32];
                const float4 cx1 = ((const float4*)s_ctx)[lane];
                const float4 cx2 = ((const float4*)s_ctx)[lane + 32];
                for (int rr = 0; rr < nr; rr++) {
                    const int lrow = r0 + rr;
                    const int row  = OSL * rank + lrow;
                    const float4* wo = (const float4*)(W_out + (size_t)row * 512);
                    const float4 a0 = wo[lane], a1 = wo[lane + 32];
                    const float4 a2 = wo[lane + 64], a3 = wo[lane + 96];
                    float acc = a0.x * h1.x + a0.y * h1.y + a0.z * h1.z + a0.w * h1.w
                              + a1.x * h2.x + a1.y * h2.y + a1.z * h2.z + a1.w * h2.w
                              + a2.x * cx1.x + a2.y * cx1.y + a2.z * cx1.z + a2.w * cx1.w
                              + a3.x * cx2.x + a3.y * cx2.y + a3.z * cx2.z + a3.w * cx2.w;
                    acc = warp_sum(acc);
                    if (lane == 0) s_logits[lrow] = acc + b_out[row];
                }
            }
            // order E-warp s_logits stores before warp 24's read (warps 24-31 only)
            asm volatile("bar.sync 1, 256;" ::: "memory");
            if (t > 0 && w == 24) {
                float lv = (lane < OSL) ? s_logits[lane] : -1e30f;
                const float lm = warp_max(lv);
                float le = (lane < OSL) ? __expf(lv - lm) : 0.f;
                le = warp_sum(le);
                if (lane == 0) {
#pragma unroll
                    for (int p = 0; p < CL; p++) {
                        float* d = clu.map_shared_rank(&s_oms[rank][0], p);
                        d[0] = lm; d[1] = le;
                    }
                }
            }
        }
        clu.sync();   // #1: h_t + oms(t-1) visible everywhere

        // ---- warp 31: write output for t-1 --------------------------------
        if (t > 0 && w == 31) {
            float M2 = -1e30f;
#pragma unroll
            for (int p = 0; p < CL; p++) M2 = fmaxf(M2, s_oms[p][0]);
            float S2 = 0.f;
#pragma unroll
            for (int p = 0; p < CL; p++) S2 += s_oms[p][1] * __expf(s_oms[p][0] - M2);
            const float off = M2 + __logf(S2);
            if (lane < OSL)
                pred_out[(size_t)(b * T_DEC + (t - 1)) * IDIM + OSL * rank + lane] =
                    s_logits[lane] - off;
        }

        // ---- B: dec_proj slice rows [32*rank, +32), parallel broadcast ----
        {
            const float4 h1 = ((const float4*)s_hbuf[nb])[lane];
            const float4 h2 = ((const float4*)s_hbuf[nb])[lane + 32];
            const int row = ASL * rank + w;
            const float4* wd = (const float4*)(W_dec + (size_t)row * 256);
            const float4 wa = wd[lane], wb = wd[lane + 32];
            float a1 = wa.x * h1.x + wa.y * h1.y + wa.z * h1.z + wa.w * h1.w
                     + wb.x * h2.x + wb.y * h2.y + wb.z * h2.z + wb.w * h2.w;
            a1 = warp_sum(a1);
            if (lane < CL)
                *clu.map_shared_rank(&s_dp[row], lane) = a1 + b_attn[row];
        }
        clu.sync();   // #2: full dec_proj visible

        // ---- C: exp(scores) directly, ILP-2 unrolled ----------------------
        {
            const float4 dpv = ((const float4*)s_dp)[lane];
            for (int tt = w; tt < TSL; tt += 64) {
                const int tt2 = tt + 32;
                const bool has2 = (tt2 < TSL);
                const float4 e1 = ep4[(size_t)(tbase + tt) * 32 + lane];
                float4 e2;
                if (has2) e2 = ep4[(size_t)(tbase + tt2) * 32 + lane];
                float a1 = fast_tanh(e1.x + dpv.x) * vreg.x
                         + fast_tanh(e1.y + dpv.y) * vreg.y
                         + fast_tanh(e1.z + dpv.z) * vreg.z
                         + fast_tanh(e1.w + dpv.w) * vreg.w;
                float a2 = 0.f;
                if (has2)
                    a2 = fast_tanh(e2.x + dpv.x) * vreg.x
                       + fast_tanh(e2.y + dpv.y) * vreg.y
                       + fast_tanh(e2.z + dpv.z) * vreg.z
                       + fast_tanh(e2.w + dpv.w) * vreg.w;
#pragma unroll
                for (int o = 16; o > 0; o >>= 1) {
                    a1 += __shfl_xor_sync(0xffffffffu, a1, o);
                    a2 += __shfl_xor_sync(0xffffffffu, a2, o);
                }
                if (lane == 0) {
                    s_e[tt] = __expf(a1);       // |score| <= sum|v_attn| ~ 5
                    if (has2) s_e[tt2] = __expf(a2);
                }
            }
        }
        __syncthreads();

        // ---- exp-sum (200 values): single-warp, sum only ------------------
        if (w == 0) {
            float s = 0.f;
#pragma unroll
            for (int k = 0; k < 7; k++) {
                const int i = lane + 32 * k;
                if (i < TSL) s += s_e[i];
            }
            s = warp_sum(s);
            if (lane == 0) s_bsum = s;
        }
        __syncthreads();

        // ---- D: local ctx partial (unnormalized exp weights) --------------
        {
            const int q  = tid >> 6;
            const int c4 = tid & 63;
            float4 acc = make_float4(0.f, 0.f, 0.f, 0.f);
            for (int tt = q; tt < TSL; tt += 16) {
                const float wgt = s_e[tt];
                const float4 ev = ef4[(size_t)(tbase + tt) * 64 + c4];
                acc.x += wgt * ev.x; acc.y += wgt * ev.y;
                acc.z += wgt * ev.z; acc.w += wgt * ev.w;
            }
            ((float4*)s_ctxp[q])[c4] = acc;
        }
        __syncthreads();
        if (tid < 64) {
            float4 r4 = make_float4(0.f, 0.f, 0.f, 0.f);
#pragma unroll
            for (int qq = 0; qq < 16; qq++) {
                const float4 p4 = ((const float4*)s_ctxp[qq])[tid];
                r4.x += p4.x; r4.y += p4.y; r4.z += p4.z; r4.w += p4.w;
            }
#pragma unroll
            for (int p = 0; p < CL; p++)
                ((float4*)clu.map_shared_rank(&s_ctxpart[rank][0], p))[tid] = r4;
        }
        if (tid == 0) {
#pragma unroll
            for (int p = 0; p < CL; p++)
                *clu.map_shared_rank(&s_ms[rank], p) = s_bsum;
        }
        clu.sync();   // #3: ctx partials + exp-sums visible

        // ---- merge: global sum + ctx + attn record ------------------------
        const float S = s_ms[0] + s_ms[1] + s_ms[2] + s_ms[3];
        const float invS = 1.f / S;
        if (tid < 64) {
            float4 r4 = make_float4(0.f, 0.f, 0.f, 0.f);
#pragma unroll
            for (int p = 0; p < CL; p++) {
                const float4 p4 = ((const float4*)&s_ctxpart[p][0])[tid];
                r4.x += p4.x; r4.y += p4.y; r4.z += p4.z; r4.w += p4.w;
            }
            r4.x *= invS; r4.y *= invS; r4.z *= invS; r4.w *= invS;
            ((float4*)s_ctx)[tid] = r4;
        }
        if (tid >= 64 && tid < 64 + TSL / 4) {
            const int i = tid - 64;
            float4 e4 = ((const float4*)s_e)[i];
            e4.x *= invS; e4.y *= invS; e4.z *= invS; e4.w *= invS;
            ((float4*)(attn_out + (size_t)(b * T_DEC + t) * T_ENC + tbase))[i] = e4;
        }
        __syncthreads();

        // ---- convert h_t/ctx_t to fp16 + prefetch gx(t+1) -----------------
        if (tid < 128) {
            s_hh2[tid] = __floats2half2_rn(s_hbuf[nb][2 * tid], s_hbuf[nb][2 * tid + 1]);
            s_ch2[tid] = __floats2half2_rn(s_ctx[2 * tid], s_ctx[2 * tid + 1]);
        }
        if (t + 1 < T_DEC && tid >= 128 && tid < 128 + NROWS) {
            const int i = tid - 128;
            const float* gxn = g_gx + (size_t)(b * T_DEC + t + 1) * 768;
            const int g = i / GSL, u = i % GSL;
            s_gx[i] = gxn[g * GDIM + GSL * rank + u];
        }
        __syncthreads();
    }

    // ===== Flush: output phase for final step T_DEC-1 ======================
    {
        const int cbf = T_DEC & 1;   // buffer holding h_{T_DEC-1}
        if (w >= 24) {
            const int ew = w - 24;
            const int r0 = (ew < 4) ? ew * 3 : 12 + (ew - 4) * 2;
            const int nr = (ew < 4) ? 3 : 2;
            const float4 h1  = ((const float4*)s_hbuf[cbf])[lane];
            const float4 h2  = ((const float4*)s_hbuf[cbf])[lane + 32];
            const float4 cx1 = ((const float4*)s_ctx)[lane];
            const float4 cx2 = ((const float4*)s_ctx)[lane + 32];
            for (int rr = 0; rr < nr; rr++) {
                const int lrow = r0 + rr;
                const int row  = OSL * rank + lrow;
                const float4* wo = (const float4*)(W_out + (size_t)row * 512);
                const float4 a0 = wo[lane], a1 = wo[lane + 32];
                const float4 a2 = wo[lane + 64], a3 = wo[lane + 96];
                float acc = a0.x * h1.x + a0.y * h1.y + a0.z * h1.z + a0.w * h1.w
                          + a1.x * h2.x + a1.y * h2.y + a1.z * h2.z + a1.w * h2.w
                          + a2.x * cx1.x + a2.y * cx1.y + a2.z * cx1.z + a2.w * cx1.w
                          + a3.x * cx2.x + a3.y * cx2.y + a3.z * cx2.z + a3.w * cx2.w;
                acc = warp_sum(acc);
                if (lane == 0) s_logits[lrow] = acc + b_out[row];
            }
        }
        __syncthreads();
        if (w == 24) {
            float lv = (lane < OSL) ? s_logits[lane] : -1e30f;
            const float lm = warp_max(lv);
            float le = (lane < OSL) ? __expf(lv - lm) : 0.f;
            le = warp_sum(le);
            if (lane == 0) {
#pragma unroll
                for (int p = 0; p < CL; p++) {
                    float* d = clu.map_shared_rank(&s_oms[rank][0], p);
                    d[0] = lm; d[1] = le;
                }
            }
        }
        clu.sync();
        if (w == 31) {
            float M2 = -1e30f;
#pragma unroll
            for (int p = 0; p < CL; p++) M2 = fmaxf(M2, s_oms[p][0]);
            float S2 = 0.f;
#pragma unroll
            for (int p = 0; p < CL; p++) S2 += s_oms[p][1] * __expf(s_oms[p][0] - M2);
            const float off = M2 + __logf(S2);
            if (lane < OSL)
                pred_out[(size_t)(b * T_DEC + (T_DEC - 1)) * IDIM + OSL * rank + lane] =
                    s_logits[lane] - off;
        }
    }
}

// ---------------------------------------------------------------------------
extern "C" void kernel_launch(void* const* d_in, const int* in_sizes, int n_in,
                              void* d_out, int out_size)
{
    const float* enc_feat = (const float*)d_in[0];
    const float* gt       = (const float*)d_in[1];
    const float* W_ih     = (const float*)d_in[2];
    const float* W_hh     = (const float*)d_in[3];
    const float* b_ih     = (const float*)d_in[4];
    const float* b_hh     = (const float*)d_in[5];
    const float* W_enc    = (const float*)d_in[6];
    const float* W_dec    = (const float*)d_in[7];
    const float* b_attn   = (const float*)d_in[8];
    const float* v_attn   = (const float*)d_in[9];
    const float* W_out    = (const float*)d_in[10];
    const float* b_out    = (const float*)d_in[11];

    float* pred = (float*)d_out;                              // (B, T_DEC, 80)
    float* attn = (float*)d_out + (size_t)BB * T_DEC * IDIM;  // (B, T_DEC, 800)

    float* ep_ptr = nullptr;
    float* gx_ptr = nullptr;
    cudaGetSymbolAddress((void**)&ep_ptr, g_enc_proj);
    cudaGetSymbolAddress((void**)&gx_ptr, g_gx);

    static bool attr_set = false;
    if (!attr_set) {
        cudaFuncSetAttribute(decode_kernel,
                             cudaFuncAttributeMaxDynamicSharedMemorySize, SMEM_DYN);
        attr_set = true;
    }

    convert_weights<<<(3 * GDIM * EDIM + 255) / 256, 256>>>(W_ih, W_hh);
    gemm_abt<<<dim3(1, 400), 256>>>(enc_feat, W_enc, ep_ptr,
                                    BB * T_ENC, ADIM, EDIM, EDIM, EDIM, ADIM);
    gemm_abt<<<dim3(6, 200), 256>>>(gt, W_ih, gx_ptr,
                                    BB * T_DEC, 3 * GDIM, IDIM, IDIM, 336, 3 * GDIM);

    decode_kernel<<<BB * CL, 1024, SMEM_DYN>>>(enc_feat, b_ih, b_hh,
                                               W_dec, b_attn, v_attn, W_out, b_out,
                                               pred, attn);
}